// round 2
// baseline (speedup 1.0000x reference)
#include <cuda_runtime.h>
#include <math.h>

// Problem constants (Graph_GRU_84576495993467): N=50000, H=128, L=2, E=1.6M
constexpr int H = 128;
constexpr int NNMAX = 50048;

// Scratch (device globals; allocation-free per harness rules). ~154 MB total.
__device__ float g_aggx [NNMAX * H];
__device__ float g_aggh [NNMAX * H];
__device__ float g_aggrh[NNMAX * H];
__device__ float g_z    [NNMAX * H];
__device__ float g_rh   [NNMAX * H];
__device__ float g_hx   [NNMAX * H];

__device__ __forceinline__ float4 f4add(float4 a, float4 b) {
    return make_float4(a.x + b.x, a.y + b.y, a.z + b.z, a.w + b.w);
}

// Vectorized global reduction (sm_90+): one L2 RED op for 16 bytes.
__device__ __forceinline__ void red_add4(float* p, float4 v) {
    asm volatile("red.global.add.v4.f32 [%0], {%1, %2, %3, %4};"
                 :: "l"(p), "f"(v.x), "f"(v.y), "f"(v.z), "f"(v.w)
                 : "memory");
}

__device__ __forceinline__ float sigmoidf_(float v) {
    return 1.0f / (1.0f + __expf(-v));
}

// ---------------------------------------------------------------------------
// Zeroing kernels (agg buffers must start at 0 each call; d_out is poisoned)
// ---------------------------------------------------------------------------
__global__ void zero_xh_kernel(int n4) {
    int i = blockIdx.x * blockDim.x + threadIdx.x;
    if (i < n4) {
        float4 z = make_float4(0.f, 0.f, 0.f, 0.f);
        reinterpret_cast<float4*>(g_aggx)[i] = z;
        reinterpret_cast<float4*>(g_aggh)[i] = z;
    }
}

__global__ void zero_rh_kernel(int n4) {
    int i = blockIdx.x * blockDim.x + threadIdx.x;
    if (i < n4) {
        reinterpret_cast<float4*>(g_aggrh)[i] = make_float4(0.f, 0.f, 0.f, 0.f);
    }
}

// ---------------------------------------------------------------------------
// Scatter-add: one warp per edge; lane handles 4 contiguous floats (float4).
// Gathers are L2-resident (x/h are 25.6MB each); REDs are L2-resident too.
// ---------------------------------------------------------------------------
__global__ void scatter_xh_kernel(const float* __restrict__ x,
                                  const float* __restrict__ hl,
                                  const int* __restrict__ src,
                                  const int* __restrict__ dst, int E) {
    int gw = (blockIdx.x * blockDim.x + threadIdx.x) >> 5;
    if (gw >= E) return;
    int lane = threadIdx.x & 31;
    int s = __ldg(src + gw);
    int d = __ldg(dst + gw);
    int off = lane << 2;
    float4 xv = __ldg(reinterpret_cast<const float4*>(x  + (size_t)s * H + off));
    float4 hv = __ldg(reinterpret_cast<const float4*>(hl + (size_t)s * H + off));
    red_add4(g_aggx + (size_t)d * H + off, xv);
    red_add4(g_aggh + (size_t)d * H + off, hv);
}

__global__ void scatter_rh_kernel(const int* __restrict__ src,
                                  const int* __restrict__ dst, int E) {
    int gw = (blockIdx.x * blockDim.x + threadIdx.x) >> 5;
    if (gw >= E) return;
    int lane = threadIdx.x & 31;
    int s = __ldg(src + gw);
    int d = __ldg(dst + gw);
    int off = lane << 2;
    float4 rv = __ldg(reinterpret_cast<const float4*>(g_rh + (size_t)s * H + off));
    red_add4(g_aggrh + (size_t)d * H + off, rv);
}

// ---------------------------------------------------------------------------
// GEMM A: C = [ax | ah] (N x 256) @ B2 (256 x 384), tiled 128x128x16 SIMT fp32.
// blockIdx.y = gate-pair j: 0 -> z (W0,W1), 1 -> r (W2,W3), 2 -> hx (W4 only).
// Epilogue fuses bias, sigmoid, r*h, and stores to g_z / g_rh / g_hx.
// ---------------------------------------------------------------------------
__global__ __launch_bounds__(256)
void gemmA_kernel(const float* __restrict__ x, const float* __restrict__ hl,
                  const float* __restrict__ Wl, const float* __restrict__ bl,
                  int Nn) {
    __shared__ float As[16][132];   // padded: 132*4 bytes is 16B-multiple
    __shared__ float Bs[16][128];

    const int j  = blockIdx.y;
    const int m0 = blockIdx.x * 128;
    const int tid = threadIdx.x;
    const int tx = tid & 15;
    const int ty = tid >> 4;

    float acc[8][8];
#pragma unroll
    for (int r = 0; r < 8; r++)
#pragma unroll
        for (int c = 0; c < 8; c++) acc[r][c] = 0.f;

    for (int kt = 0; kt < 16; ++kt) {           // K = 256, BK = 16
        const int k0 = kt * 16;
        // Load A tile (fused ax/ah construction), store transposed As[k][m]
#pragma unroll
        for (int it = 0; it < 2; ++it) {
            int idx = tid + it * 256;
            int row = idx >> 2;
            int kq  = (idx & 3) << 2;
            int m   = m0 + row;
            int kg  = k0 + kq;
            float4 v = make_float4(0.f, 0.f, 0.f, 0.f);
            if (m < Nn) {
                if (kg < H) {
                    v = f4add(__ldg(reinterpret_cast<const float4*>(x      + (size_t)m * H + kg)),
                              __ldg(reinterpret_cast<const float4*>(g_aggx + (size_t)m * H + kg)));
                } else {
                    v = f4add(__ldg(reinterpret_cast<const float4*>(hl     + (size_t)m * H + kg - H)),
                              __ldg(reinterpret_cast<const float4*>(g_aggh + (size_t)m * H + kg - H)));
                }
            }
            As[kq + 0][row] = v.x;
            As[kq + 1][row] = v.y;
            As[kq + 2][row] = v.z;
            As[kq + 3][row] = v.w;
        }
        // Load B tile: rows k of stacked weights. k<128 -> W[2j], else W[2j+1] (j<2)
#pragma unroll
        for (int it = 0; it < 2; ++it) {
            int idx = tid + it * 256;
            int kk  = idx >> 5;
            int nq  = (idx & 31) << 2;
            int kg  = k0 + kk;
            float4 v = make_float4(0.f, 0.f, 0.f, 0.f);
            if (kg < H)
                v = __ldg(reinterpret_cast<const float4*>(Wl + ((size_t)(2 * j) * H + kg) * H + nq));
            else if (j < 2)
                v = __ldg(reinterpret_cast<const float4*>(Wl + ((size_t)(2 * j + 1) * H + (kg - H)) * H + nq));
            *reinterpret_cast<float4*>(&Bs[kk][nq]) = v;
        }
        __syncthreads();
#pragma unroll
        for (int kk = 0; kk < 16; ++kk) {
            float a[8], bb[8];
            *reinterpret_cast<float4*>(&a[0])  = *reinterpret_cast<const float4*>(&As[kk][ty * 8]);
            *reinterpret_cast<float4*>(&a[4])  = *reinterpret_cast<const float4*>(&As[kk][ty * 8 + 4]);
            *reinterpret_cast<float4*>(&bb[0]) = *reinterpret_cast<const float4*>(&Bs[kk][tx * 8]);
            *reinterpret_cast<float4*>(&bb[4]) = *reinterpret_cast<const float4*>(&Bs[kk][tx * 8 + 4]);
#pragma unroll
            for (int r = 0; r < 8; r++)
#pragma unroll
                for (int c = 0; c < 8; c++)
                    acc[r][c] = fmaf(a[r], bb[c], acc[r][c]);
        }
        __syncthreads();
    }

    // Epilogue: combined biases b[2j] + b[2j+1]
    const int g0 = 2 * j;
    float bias[8];
#pragma unroll
    for (int c = 0; c < 8; c++) {
        int n = tx * 8 + c;
        bias[c] = __ldg(bl + g0 * H + n) + __ldg(bl + (g0 + 1) * H + n);
    }
#pragma unroll
    for (int r = 0; r < 8; r++) {
        int m = m0 + ty * 8 + r;
        if (m >= Nn) continue;
        size_t base = (size_t)m * H + tx * 8;
        if (j == 0) {
#pragma unroll
            for (int c = 0; c < 8; c++)
                g_z[base + c] = sigmoidf_(acc[r][c] + bias[c]);
        } else if (j == 1) {
#pragma unroll
            for (int c = 0; c < 8; c++)
                g_rh[base + c] = sigmoidf_(acc[r][c] + bias[c]) * __ldg(hl + base + c);
        } else {
#pragma unroll
            for (int c = 0; c < 8; c++)
                g_hx[base + c] = acc[r][c] + bias[c];
        }
    }
}

// ---------------------------------------------------------------------------
// GEMM C: C = (rh + agg(rh)) (N x 128) @ W5 (128 x 128).
// Epilogue: h_tilde = tanh(C + hx); out = z*h + (1-z)*h_tilde  -> d_out[layer]
// ---------------------------------------------------------------------------
__global__ __launch_bounds__(256)
void gemmC_kernel(const float* __restrict__ hl, const float* __restrict__ Wl,
                  float* __restrict__ out, int Nn) {
    __shared__ float As[16][132];
    __shared__ float Bs[16][128];

    const int m0 = blockIdx.x * 128;
    const int tid = threadIdx.x;
    const int tx = tid & 15;
    const int ty = tid >> 4;
    const float* W5 = Wl + (size_t)5 * H * H;

    float acc[8][8];
#pragma unroll
    for (int r = 0; r < 8; r++)
#pragma unroll
        for (int c = 0; c < 8; c++) acc[r][c] = 0.f;

    for (int kt = 0; kt < 8; ++kt) {            // K = 128, BK = 16
        const int k0 = kt * 16;
#pragma unroll
        for (int it = 0; it < 2; ++it) {
            int idx = tid + it * 256;
            int row = idx >> 2;
            int kq  = (idx & 3) << 2;
            int m   = m0 + row;
            int kg  = k0 + kq;
            float4 v = make_float4(0.f, 0.f, 0.f, 0.f);
            if (m < Nn) {
                v = f4add(__ldg(reinterpret_cast<const float4*>(g_rh    + (size_t)m * H + kg)),
                          __ldg(reinterpret_cast<const float4*>(g_aggrh + (size_t)m * H + kg)));
            }
            As[kq + 0][row] = v.x;
            As[kq + 1][row] = v.y;
            As[kq + 2][row] = v.z;
            As[kq + 3][row] = v.w;
        }
#pragma unroll
        for (int it = 0; it < 2; ++it) {
            int idx = tid + it * 256;
            int kk  = idx >> 5;
            int nq  = (idx & 31) << 2;
            int kg  = k0 + kk;
            *reinterpret_cast<float4*>(&Bs[kk][nq]) =
                __ldg(reinterpret_cast<const float4*>(W5 + (size_t)kg * H + nq));
        }
        __syncthreads();
#pragma unroll
        for (int kk = 0; kk < 16; ++kk) {
            float a[8], bb[8];
            *reinterpret_cast<float4*>(&a[0])  = *reinterpret_cast<const float4*>(&As[kk][ty * 8]);
            *reinterpret_cast<float4*>(&a[4])  = *reinterpret_cast<const float4*>(&As[kk][ty * 8 + 4]);
            *reinterpret_cast<float4*>(&bb[0]) = *reinterpret_cast<const float4*>(&Bs[kk][tx * 8]);
            *reinterpret_cast<float4*>(&bb[4]) = *reinterpret_cast<const float4*>(&Bs[kk][tx * 8 + 4]);
#pragma unroll
            for (int r = 0; r < 8; r++)
#pragma unroll
                for (int c = 0; c < 8; c++)
                    acc[r][c] = fmaf(a[r], bb[c], acc[r][c]);
        }
        __syncthreads();
    }

#pragma unroll
    for (int r = 0; r < 8; r++) {
        int m = m0 + ty * 8 + r;
        if (m >= Nn) continue;
        size_t base = (size_t)m * H + tx * 8;
#pragma unroll
        for (int c = 0; c < 8; c++) {
            float pre = acc[r][c] + g_hx[base + c];
            float ht  = tanhf(pre);
            float z   = g_z[base + c];
            float hv  = __ldg(hl + base + c);
            out[base + c] = z * hv + (1.f - z) * ht;
        }
    }
}

// ---------------------------------------------------------------------------
// Launch: per layer: zero -> scatter(x,h) -> gemmA -> zero -> scatter(rh) -> gemmC
// All plain default-stream launches (graph-capturable, allocation-free).
// ---------------------------------------------------------------------------
extern "C" void kernel_launch(void* const* d_in, const int* in_sizes, int n_in,
                              void* d_out, int out_size) {
    const float* inp = (const float*)d_in[0];
    const int*   edg = (const int*)  d_in[1];
    const float* h   = (const float*)d_in[2];
    const float* W   = (const float*)d_in[3];
    const float* b   = (const float*)d_in[4];
    float* out = (float*)d_out;

    const int Nn = in_sizes[0] / H;          // 50000
    const int E  = in_sizes[1] / 2;          // 1,600,000
    const int L  = in_sizes[2] / (Nn * H);   // 2

    const int* src = edg;
    const int* dst = edg + E;

    const int n4      = (Nn * H) / 4;
    const int zblocks = (n4 + 255) / 256;
    const int sblocks = (E * 32 + 255) / 256;   // one warp per edge
    const int mblocks = (Nn + 127) / 128;

    for (int i = 0; i < L; i++) {
        const float* x  = (i == 0) ? inp : out + (size_t)(i - 1) * Nn * H;
        const float* hl = h + (size_t)i * Nn * H;
        const float* Wl = W + (size_t)i * 6 * H * H;
        const float* bl = b + (size_t)i * 6 * H;
        float* outl = out + (size_t)i * Nn * H;

        zero_xh_kernel<<<zblocks, 256>>>(n4);
        scatter_xh_kernel<<<sblocks, 256>>>(x, hl, src, dst, E);
        gemmA_kernel<<<dim3(mblocks, 3), 256>>>(x, hl, Wl, bl, Nn);
        zero_rh_kernel<<<zblocks, 256>>>(n4);
        scatter_rh_kernel<<<sblocks, 256>>>(src, dst, E);
        gemmC_kernel<<<mblocks, 256>>>(hl, Wl, outl, Nn);
    }
}

// round 3
// speedup vs baseline: 1.1407x; 1.1407x over previous
#include <cuda_runtime.h>
#include <math.h>

// Problem constants (Graph_GRU_84576495993467): N=50000, H=128, L=2, E=1.6M
constexpr int H = 128;
constexpr int NNMAX = 50048;
constexpr int EMAX  = 1605632;

// Scratch (device globals; allocation-free). ~140 MB total.
__device__ float g_axh [NNMAX * 256];  // [ax | ah] fused A-operand (N x 256)
__device__ float g_arh [NNMAX * H];    // rh + agg(rh)
__device__ float g_z   [NNMAX * H];
__device__ float g_rh  [NNMAX * H];
__device__ float g_hx  [NNMAX * H];
__device__ int   g_cnt   [NNMAX];
__device__ int   g_rowptr[NNMAX + 1];
__device__ int   g_cursor[NNMAX];
__device__ int   g_col   [EMAX];

__device__ __forceinline__ float4 f4add(float4 a, float4 b) {
    return make_float4(a.x + b.x, a.y + b.y, a.z + b.z, a.w + b.w);
}
__device__ __forceinline__ float sigmoidf_(float v) {
    return 1.0f / (1.0f + __expf(-v));
}

// ---------------------------------------------------------------------------
// CSR build (per call; edges fixed per call so this amortizes over 6 aggs)
// ---------------------------------------------------------------------------
__global__ void csr_zero_kernel(int Nn) {
    int i = blockIdx.x * blockDim.x + threadIdx.x;
    if (i < Nn) g_cnt[i] = 0;
}

__global__ void csr_hist_kernel(const int* __restrict__ dst, int E) {
    int i = blockIdx.x * blockDim.x + threadIdx.x;
    if (i < E) atomicAdd(&g_cnt[__ldg(dst + i)], 1);
}

// One-block exclusive scan over N counts -> rowptr (+ cursor copy)
__global__ __launch_bounds__(1024)
void csr_scan_kernel(int Nn) {
    __shared__ int ssum[1024];
    const int t = threadIdx.x;
    const int chunk = (Nn + 1023) >> 10;
    const int lo = t * chunk;
    const int hi = min(lo + chunk, Nn);
    int s = 0;
    for (int i = lo; i < hi; ++i) s += g_cnt[i];
    ssum[t] = s;
    __syncthreads();
    // Hillis-Steele inclusive scan over 1024 partials
    for (int d = 1; d < 1024; d <<= 1) {
        int v = ssum[t];
        if (t >= d) v += ssum[t - d];
        __syncthreads();
        ssum[t] = v;
        __syncthreads();
    }
    int off = (t > 0) ? ssum[t - 1] : 0;
    for (int i = lo; i < hi; ++i) {
        int c = g_cnt[i];
        g_rowptr[i] = off;
        g_cursor[i] = off;
        off += c;
    }
    if (hi == Nn && lo <= Nn) g_rowptr[Nn] = off;
}

__global__ void csr_fill_kernel(const int* __restrict__ src,
                                const int* __restrict__ dst, int E) {
    int i = blockIdx.x * blockDim.x + threadIdx.x;
    if (i < E) {
        int d = __ldg(dst + i);
        int pos = atomicAdd(&g_cursor[d], 1);
        g_col[pos] = __ldg(src + i);
    }
}

// ---------------------------------------------------------------------------
// Gather: one warp per node; lane owns 4 contiguous floats. No atomics.
// Writes fused A-operand rows: g_axh[n] = [x[n]+agg(x) | h[n]+agg(h)]
// ---------------------------------------------------------------------------
__global__ __launch_bounds__(256)
void gather_xh_kernel(const float* __restrict__ x,
                      const float* __restrict__ hl, int Nn) {
    int w = (blockIdx.x * blockDim.x + threadIdx.x) >> 5;
    if (w >= Nn) return;
    const int lane = threadIdx.x & 31;
    const int off = lane << 2;
    const int start = __ldg(g_rowptr + w);
    const int end   = __ldg(g_rowptr + w + 1);

    float4 ax = __ldg(reinterpret_cast<const float4*>(x  + (size_t)w * H + off));
    float4 ah = __ldg(reinterpret_cast<const float4*>(hl + (size_t)w * H + off));

    for (int j = start; j < end; j += 32) {
        int rem = end - j;
        int idx = (lane < rem) ? __ldg(g_col + j + lane) : 0;
        int m = min(rem, 32);
#pragma unroll 4
        for (int k = 0; k < m; ++k) {
            int s = __shfl_sync(0xffffffffu, idx, k);
            ax = f4add(ax, __ldg(reinterpret_cast<const float4*>(x  + (size_t)s * H + off)));
            ah = f4add(ah, __ldg(reinterpret_cast<const float4*>(hl + (size_t)s * H + off)));
        }
    }
    *reinterpret_cast<float4*>(g_axh + (size_t)w * 256 + off)       = ax;
    *reinterpret_cast<float4*>(g_axh + (size_t)w * 256 + 128 + off) = ah;
}

__global__ __launch_bounds__(256)
void gather_rh_kernel(int Nn) {
    int w = (blockIdx.x * blockDim.x + threadIdx.x) >> 5;
    if (w >= Nn) return;
    const int lane = threadIdx.x & 31;
    const int off = lane << 2;
    const int start = __ldg(g_rowptr + w);
    const int end   = __ldg(g_rowptr + w + 1);

    float4 a = *reinterpret_cast<const float4*>(g_rh + (size_t)w * H + off);

    for (int j = start; j < end; j += 32) {
        int rem = end - j;
        int idx = (lane < rem) ? __ldg(g_col + j + lane) : 0;
        int m = min(rem, 32);
#pragma unroll 4
        for (int k = 0; k < m; ++k) {
            int s = __shfl_sync(0xffffffffu, idx, k);
            a = f4add(a, *reinterpret_cast<const float4*>(g_rh + (size_t)s * H + off));
        }
    }
    *reinterpret_cast<float4*>(g_arh + (size_t)w * H + off) = a;
}

// ---------------------------------------------------------------------------
// GEMM A: C = axh (N x 256) @ B2 (256 x 384), tiled 128x128x16 SIMT fp32.
// blockIdx.y = j: 0 -> z (W0,W1, K=256), 1 -> r (W2,W3, K=256), 2 -> hx (W4, K=128)
// ---------------------------------------------------------------------------
__global__ __launch_bounds__(256)
void gemmA_kernel(const float* __restrict__ hl,
                  const float* __restrict__ Wl, const float* __restrict__ bl,
                  int Nn) {
    __shared__ float As[16][132];
    __shared__ float Bs[16][128];

    const int j  = blockIdx.y;
    const int m0 = blockIdx.x * 128;
    const int tid = threadIdx.x;
    const int tx = tid & 15;
    const int ty = tid >> 4;
    const int ktmax = (j == 2) ? 8 : 16;

    float acc[8][8];
#pragma unroll
    for (int r = 0; r < 8; r++)
#pragma unroll
        for (int c = 0; c < 8; c++) acc[r][c] = 0.f;

    for (int kt = 0; kt < ktmax; ++kt) {
        const int k0 = kt * 16;
#pragma unroll
        for (int it = 0; it < 2; ++it) {
            int idx = tid + it * 256;
            int row = idx >> 2;
            int kq  = (idx & 3) << 2;
            int m   = m0 + row;
            int kg  = k0 + kq;
            float4 v = make_float4(0.f, 0.f, 0.f, 0.f);
            if (m < Nn)
                v = __ldg(reinterpret_cast<const float4*>(g_axh + (size_t)m * 256 + kg));
            As[kq + 0][row] = v.x;
            As[kq + 1][row] = v.y;
            As[kq + 2][row] = v.z;
            As[kq + 3][row] = v.w;
        }
#pragma unroll
        for (int it = 0; it < 2; ++it) {
            int idx = tid + it * 256;
            int kk  = idx >> 5;
            int nq  = (idx & 31) << 2;
            int kg  = k0 + kk;
            float4 v;
            if (kg < H)
                v = __ldg(reinterpret_cast<const float4*>(Wl + ((size_t)(2 * j) * H + kg) * H + nq));
            else
                v = __ldg(reinterpret_cast<const float4*>(Wl + ((size_t)(2 * j + 1) * H + (kg - H)) * H + nq));
            *reinterpret_cast<float4*>(&Bs[kk][nq]) = v;
        }
        __syncthreads();
#pragma unroll
        for (int kk = 0; kk < 16; ++kk) {
            float a[8], bb[8];
            *reinterpret_cast<float4*>(&a[0])  = *reinterpret_cast<const float4*>(&As[kk][ty * 8]);
            *reinterpret_cast<float4*>(&a[4])  = *reinterpret_cast<const float4*>(&As[kk][ty * 8 + 4]);
            *reinterpret_cast<float4*>(&bb[0]) = *reinterpret_cast<const float4*>(&Bs[kk][tx * 8]);
            *reinterpret_cast<float4*>(&bb[4]) = *reinterpret_cast<const float4*>(&Bs[kk][tx * 8 + 4]);
#pragma unroll
            for (int r = 0; r < 8; r++)
#pragma unroll
                for (int c = 0; c < 8; c++)
                    acc[r][c] = fmaf(a[r], bb[c], acc[r][c]);
        }
        __syncthreads();
    }

    const int g0 = 2 * j;
    float bias[8];
#pragma unroll
    for (int c = 0; c < 8; c++) {
        int n = tx * 8 + c;
        bias[c] = __ldg(bl + g0 * H + n) + __ldg(bl + (g0 + 1) * H + n);
    }
#pragma unroll
    for (int r = 0; r < 8; r++) {
        int m = m0 + ty * 8 + r;
        if (m >= Nn) continue;
        size_t base = (size_t)m * H + tx * 8;
        if (j == 0) {
#pragma unroll
            for (int c = 0; c < 8; c++)
                g_z[base + c] = sigmoidf_(acc[r][c] + bias[c]);
        } else if (j == 1) {
#pragma unroll
            for (int c = 0; c < 8; c++)
                g_rh[base + c] = sigmoidf_(acc[r][c] + bias[c]) * __ldg(hl + base + c);
        } else {
#pragma unroll
            for (int c = 0; c < 8; c++)
                g_hx[base + c] = acc[r][c] + bias[c];
        }
    }
}

// ---------------------------------------------------------------------------
// GEMM C: C = arh (N x 128) @ W5 (128 x 128).
// Epilogue: h_tilde = tanh(C + hx); out = z*h + (1-z)*h_tilde
// ---------------------------------------------------------------------------
__global__ __launch_bounds__(256)
void gemmC_kernel(const float* __restrict__ hl, const float* __restrict__ Wl,
                  float* __restrict__ out, int Nn) {
    __shared__ float As[16][132];
    __shared__ float Bs[16][128];

    const int m0 = blockIdx.x * 128;
    const int tid = threadIdx.x;
    const int tx = tid & 15;
    const int ty = tid >> 4;
    const float* W5 = Wl + (size_t)5 * H * H;

    float acc[8][8];
#pragma unroll
    for (int r = 0; r < 8; r++)
#pragma unroll
        for (int c = 0; c < 8; c++) acc[r][c] = 0.f;

    for (int kt = 0; kt < 8; ++kt) {
        const int k0 = kt * 16;
#pragma unroll
        for (int it = 0; it < 2; ++it) {
            int idx = tid + it * 256;
            int row = idx >> 2;
            int kq  = (idx & 3) << 2;
            int m   = m0 + row;
            int kg  = k0 + kq;
            float4 v = make_float4(0.f, 0.f, 0.f, 0.f);
            if (m < Nn)
                v = *reinterpret_cast<const float4*>(g_arh + (size_t)m * H + kg);
            As[kq + 0][row] = v.x;
            As[kq + 1][row] = v.y;
            As[kq + 2][row] = v.z;
            As[kq + 3][row] = v.w;
        }
#pragma unroll
        for (int it = 0; it < 2; ++it) {
            int idx = tid + it * 256;
            int kk  = idx >> 5;
            int nq  = (idx & 31) << 2;
            int kg  = k0 + kk;
            *reinterpret_cast<float4*>(&Bs[kk][nq]) =
                __ldg(reinterpret_cast<const float4*>(W5 + (size_t)kg * H + nq));
        }
        __syncthreads();
#pragma unroll
        for (int kk = 0; kk < 16; ++kk) {
            float a[8], bb[8];
            *reinterpret_cast<float4*>(&a[0])  = *reinterpret_cast<const float4*>(&As[kk][ty * 8]);
            *reinterpret_cast<float4*>(&a[4])  = *reinterpret_cast<const float4*>(&As[kk][ty * 8 + 4]);
            *reinterpret_cast<float4*>(&bb[0]) = *reinterpret_cast<const float4*>(&Bs[kk][tx * 8]);
            *reinterpret_cast<float4*>(&bb[4]) = *reinterpret_cast<const float4*>(&Bs[kk][tx * 8 + 4]);
#pragma unroll
            for (int r = 0; r < 8; r++)
#pragma unroll
                for (int c = 0; c < 8; c++)
                    acc[r][c] = fmaf(a[r], bb[c], acc[r][c]);
        }
        __syncthreads();
    }

#pragma unroll
    for (int r = 0; r < 8; r++) {
        int m = m0 + ty * 8 + r;
        if (m >= Nn) continue;
        size_t base = (size_t)m * H + tx * 8;
#pragma unroll
        for (int c = 0; c < 8; c++) {
            float pre = acc[r][c] + g_hx[base + c];
            float ht  = tanhf(pre);
            float z   = g_z[base + c];
            float hv  = __ldg(hl + base + c);
            out[base + c] = z * hv + (1.f - z) * ht;
        }
    }
}

// ---------------------------------------------------------------------------
// Launch: CSR build once, then per layer:
//   gather(xh) -> gemmA -> gather(rh) -> gemmC
// ---------------------------------------------------------------------------
extern "C" void kernel_launch(void* const* d_in, const int* in_sizes, int n_in,
                              void* d_out, int out_size) {
    const float* inp = (const float*)d_in[0];
    const int*   edg = (const int*)  d_in[1];
    const float* h   = (const float*)d_in[2];
    const float* W   = (const float*)d_in[3];
    const float* b   = (const float*)d_in[4];
    float* out = (float*)d_out;

    const int Nn = in_sizes[0] / H;          // 50000
    const int E  = in_sizes[1] / 2;          // 1,600,000
    const int L  = in_sizes[2] / (Nn * H);   // 2

    const int* src = edg;
    const int* dst = edg + E;

    const int eblocks = (E + 255) / 256;
    const int nblocks = (Nn + 255) / 256;
    const int gblocks = (Nn * 32 + 255) / 256;   // one warp per node
    const int mblocks = (Nn + 127) / 128;

    // CSR build (by dst) — once per call, reused by all 6 aggregations
    csr_zero_kernel<<<nblocks, 256>>>(Nn);
    csr_hist_kernel<<<eblocks, 256>>>(dst, E);
    csr_scan_kernel<<<1, 1024>>>(Nn);
    csr_fill_kernel<<<eblocks, 256>>>(src, dst, E);

    for (int i = 0; i < L; i++) {
        const float* x  = (i == 0) ? inp : out + (size_t)(i - 1) * Nn * H;
        const float* hl = h + (size_t)i * Nn * H;
        const float* Wl = W + (size_t)i * 6 * H * H;
        const float* bl = b + (size_t)i * 6 * H;
        float* outl = out + (size_t)i * Nn * H;

        gather_xh_kernel<<<gblocks, 256>>>(x, hl, Nn);
        gemmA_kernel<<<dim3(mblocks, 3), 256>>>(hl, Wl, bl, Nn);
        gather_rh_kernel<<<gblocks, 256>>>(Nn);
        gemmC_kernel<<<mblocks, 256>>>(hl, Wl, outl, Nn);
    }
}

// round 6
// speedup vs baseline: 1.4160x; 1.2413x over previous
#include <cuda_runtime.h>
#include <cuda_bf16.h>
#include <math.h>
#include <stdint.h>

// Problem constants (Graph_GRU_84576495993467): N=50000, H=128, L=2, E=1.6M
constexpr int H = 128;
constexpr int NNMAX = 50048;          // 391 * 128 exactly
constexpr int EMAX  = 1605632;
constexpr int LMAX  = 2;

// Scratch (device globals; allocation-free).
__device__ __nv_bfloat16 g_axh_h[NNMAX * 256];  // split [ax|ah], hi
__device__ __nv_bfloat16 g_axh_l[NNMAX * 256];  // split [ax|ah], lo
__device__ __nv_bfloat16 g_arh_h[NNMAX * H];
__device__ __nv_bfloat16 g_arh_l[NNMAX * H];
__device__ float g_z   [NNMAX * H];
__device__ float g_rh  [NNMAX * H];
__device__ float g_hx  [NNMAX * H];
__device__ int   g_cnt   [NNMAX];
__device__ int   g_rowptr[NNMAX + 1];
__device__ int   g_cursor[NNMAX];
__device__ int   g_col   [EMAX];
// Pre-split weights, [N,K] layout for mma B operand (row.col => B col-major)
__device__ __nv_bfloat16 g_WAh[LMAX * 3 * 128 * 256];
__device__ __nv_bfloat16 g_WAl[LMAX * 3 * 128 * 256];
__device__ __nv_bfloat16 g_WCh[LMAX * 128 * 128];
__device__ __nv_bfloat16 g_WCl[LMAX * 128 * 128];

__device__ __forceinline__ float4 f4add(float4 a, float4 b) {
    return make_float4(a.x + b.x, a.y + b.y, a.z + b.z, a.w + b.w);
}
__device__ __forceinline__ float sigmoidf_(float v) {
    return 1.0f / (1.0f + __expf(-v));
}
__device__ __forceinline__ uint32_t pk(__nv_bfloat16 a, __nv_bfloat16 b) {
    __nv_bfloat162 t; t.x = a; t.y = b;
    return *reinterpret_cast<uint32_t*>(&t);
}
// Split float4 into hi/lo bf16 packed pairs.
__device__ __forceinline__ void split4(float4 v, uint2& hi, uint2& lo) {
    __nv_bfloat16 h0 = __float2bfloat16_rn(v.x);
    __nv_bfloat16 h1 = __float2bfloat16_rn(v.y);
    __nv_bfloat16 h2 = __float2bfloat16_rn(v.z);
    __nv_bfloat16 h3 = __float2bfloat16_rn(v.w);
    hi = make_uint2(pk(h0, h1), pk(h2, h3));
    lo = make_uint2(pk(__float2bfloat16_rn(v.x - __bfloat162float(h0)),
                       __float2bfloat16_rn(v.y - __bfloat162float(h1))),
                    pk(__float2bfloat16_rn(v.z - __bfloat162float(h2)),
                       __float2bfloat16_rn(v.w - __bfloat162float(h3))));
}

// mma.sync m16n8k16 bf16 -> f32, D += A*B
__device__ __forceinline__ void mma16816(float* d, const uint32_t* a, const uint32_t* b) {
    asm volatile(
        "mma.sync.aligned.m16n8k16.row.col.f32.bf16.bf16.f32 "
        "{%0,%1,%2,%3}, {%4,%5,%6,%7}, {%8,%9}, {%0,%1,%2,%3};"
        : "+f"(d[0]), "+f"(d[1]), "+f"(d[2]), "+f"(d[3])
        : "r"(a[0]), "r"(a[1]), "r"(a[2]), "r"(a[3]), "r"(b[0]), "r"(b[1]));
}

// ======================= CSR build (verified R3) ===========================
__global__ void csr_zero_kernel(int Nn) {
    int i = blockIdx.x * blockDim.x + threadIdx.x;
    if (i < Nn) g_cnt[i] = 0;
}
__global__ void csr_hist_kernel(const int* __restrict__ dst, int E) {
    int i = blockIdx.x * blockDim.x + threadIdx.x;
    if (i < E) atomicAdd(&g_cnt[__ldg(dst + i)], 1);
}
__global__ __launch_bounds__(1024)
void csr_scan_kernel(int Nn) {
    __shared__ int ssum[1024];
    const int t = threadIdx.x;
    const int chunk = (Nn + 1023) >> 10;
    const int lo = t * chunk;
    const int hi = min(lo + chunk, Nn);
    int s = 0;
    for (int i = lo; i < hi; ++i) s += g_cnt[i];
    ssum[t] = s;
    __syncthreads();
    for (int d = 1; d < 1024; d <<= 1) {
        int v = ssum[t];
        if (t >= d) v += ssum[t - d];
        __syncthreads();
        ssum[t] = v;
        __syncthreads();
    }
    int off = (t > 0) ? ssum[t - 1] : 0;
    for (int i = lo; i < hi; ++i) {
        int c = g_cnt[i];
        g_rowptr[i] = off;
        g_cursor[i] = off;
        off += c;
    }
    if (hi == Nn && lo <= Nn) g_rowptr[Nn] = off;
}
__global__ void csr_fill_kernel(const int* __restrict__ src,
                                const int* __restrict__ dst, int E) {
    int i = blockIdx.x * blockDim.x + threadIdx.x;
    if (i < E) {
        int d = __ldg(dst + i);
        int pos = atomicAdd(&g_cursor[d], 1);
        g_col[pos] = __ldg(src + i);
    }
}

// ======================= Weight pre-split ==================================
__global__ void prep_w_kernel(const float* __restrict__ W, int L) {
    int i = blockIdx.x * blockDim.x + threadIdx.x;
    const int totA = L * 3 * 128 * 256;
    const int totC = L * 128 * 128;
    if (i < totA) {
        int k = i & 255;
        int t = i >> 8;
        int n = t & 127;
        t >>= 7;
        int j = t % 3;
        int l = t / 3;
        int gsel = (k < 128) ? 2 * j : 2 * j + 1;
        int kk = k & 127;
        float v = __ldg(W + (((size_t)l * 6 + gsel) * 128 + kk) * 128 + n);
        __nv_bfloat16 hv = __float2bfloat16_rn(v);
        g_WAh[i] = hv;
        g_WAl[i] = __float2bfloat16_rn(v - __bfloat162float(hv));
    } else if (i < totA + totC) {
        int q = i - totA;
        int k = q & 127;
        int t = q >> 7;
        int n = t & 127;
        int l = t >> 7;
        float v = __ldg(W + (((size_t)l * 6 + 5) * 128 + k) * 128 + n);
        __nv_bfloat16 hv = __float2bfloat16_rn(v);
        g_WCh[q] = hv;
        g_WCl[q] = __float2bfloat16_rn(v - __bfloat162float(hv));
    }
}

// ======================= Gather kernels (now emit split bf16) ==============
__global__ __launch_bounds__(256)
void gather_xh_kernel(const float* __restrict__ x,
                      const float* __restrict__ hl, int Nn) {
    int w = (blockIdx.x * blockDim.x + threadIdx.x) >> 5;
    if (w >= Nn) return;
    const int lane = threadIdx.x & 31;
    const int off = lane << 2;
    const int start = __ldg(g_rowptr + w);
    const int end   = __ldg(g_rowptr + w + 1);

    float4 ax = __ldg(reinterpret_cast<const float4*>(x  + (size_t)w * H + off));
    float4 ah = __ldg(reinterpret_cast<const float4*>(hl + (size_t)w * H + off));

    for (int j = start; j < end; j += 32) {
        int rem = end - j;
        int idx = (lane < rem) ? __ldg(g_col + j + lane) : 0;
        int m = min(rem, 32);
#pragma unroll 4
        for (int k = 0; k < m; ++k) {
            int s = __shfl_sync(0xffffffffu, idx, k);
            ax = f4add(ax, __ldg(reinterpret_cast<const float4*>(x  + (size_t)s * H + off)));
            ah = f4add(ah, __ldg(reinterpret_cast<const float4*>(hl + (size_t)s * H + off)));
        }
    }
    uint2 hi, lo;
    split4(ax, hi, lo);
    *reinterpret_cast<uint2*>(g_axh_h + (size_t)w * 256 + off) = hi;
    *reinterpret_cast<uint2*>(g_axh_l + (size_t)w * 256 + off) = lo;
    split4(ah, hi, lo);
    *reinterpret_cast<uint2*>(g_axh_h + (size_t)w * 256 + 128 + off) = hi;
    *reinterpret_cast<uint2*>(g_axh_l + (size_t)w * 256 + 128 + off) = lo;
}

__global__ __launch_bounds__(256)
void gather_rh_kernel(int Nn) {
    int w = (blockIdx.x * blockDim.x + threadIdx.x) >> 5;
    if (w >= Nn) return;
    const int lane = threadIdx.x & 31;
    const int off = lane << 2;
    const int start = __ldg(g_rowptr + w);
    const int end   = __ldg(g_rowptr + w + 1);

    float4 a = *reinterpret_cast<const float4*>(g_rh + (size_t)w * H + off);

    for (int j = start; j < end; j += 32) {
        int rem = end - j;
        int idx = (lane < rem) ? __ldg(g_col + j + lane) : 0;
        int m = min(rem, 32);
#pragma unroll 4
        for (int k = 0; k < m; ++k) {
            int s = __shfl_sync(0xffffffffu, idx, k);
            a = f4add(a, *reinterpret_cast<const float4*>(g_rh + (size_t)s * H + off));
        }
    }
    uint2 hi, lo;
    split4(a, hi, lo);
    *reinterpret_cast<uint2*>(g_arh_h + (size_t)w * H + off) = hi;
    *reinterpret_cast<uint2*>(g_arh_l + (size_t)w * H + off) = lo;
}

// ======================= mma.sync GEMM A ===================================
// CTA: 128 rows x 128 cols (one gate, blockIdx.y = j). 8 warps, each 64x32.
// Split-bf16: D = Ah*Bh + Ah*Bl + Al*Bh  (fp32 accumulate).
// SMEM stride 40 bf16: conflict-free frag loads (checked: 20*gid+tig distinct mod 32).
constexpr int SST = 40;

__global__ __launch_bounds__(256)
void gemmA_mma(const float* __restrict__ hl, const float* __restrict__ bl,
               int layer, int Nn) {
    __shared__ __nv_bfloat16 Ah[128][SST], Al[128][SST];
    __shared__ __nv_bfloat16 Bh[128][SST], Bl[128][SST];

    const int tid  = threadIdx.x;
    const int wid  = tid >> 5;
    const int lane = tid & 31;
    const int gid  = lane >> 2;
    const int tig  = lane & 3;
    const int wm   = wid & 1;          // 2 M-warps (64 rows each)
    const int wn   = wid >> 1;         // 4 N-warps (32 cols each)
    const int j    = blockIdx.y;
    const int m0   = blockIdx.x * 128;
    const int nchunks = (j == 2) ? 4 : 8;   // K = 128 or 256, BK = 32

    const __nv_bfloat16* WAh = g_WAh + ((size_t)layer * 3 + j) * 128 * 256;
    const __nv_bfloat16* WAl = g_WAl + ((size_t)layer * 3 + j) * 128 * 256;

    const int crow = tid >> 1;          // copy: row 0..127
    const int chal = (tid & 1) * 16;    // copy: 16-col half

    float acc[4][4][4];
#pragma unroll
    for (int a = 0; a < 4; a++)
#pragma unroll
        for (int b = 0; b < 4; b++)
#pragma unroll
            for (int c = 0; c < 4; c++) acc[a][b][c] = 0.f;

    for (int kc = 0; kc < nchunks; ++kc) {
        const int k0 = kc * 32;
        {
            const uint4* s = reinterpret_cast<const uint4*>(
                g_axh_h + (size_t)(m0 + crow) * 256 + k0 + chal);
            *reinterpret_cast<uint4*>(&Ah[crow][chal])     = __ldg(s);
            *reinterpret_cast<uint4*>(&Ah[crow][chal + 8]) = __ldg(s + 1);
            s = reinterpret_cast<const uint4*>(
                g_axh_l + (size_t)(m0 + crow) * 256 + k0 + chal);
            *reinterpret_cast<uint4*>(&Al[crow][chal])     = __ldg(s);
            *reinterpret_cast<uint4*>(&Al[crow][chal + 8]) = __ldg(s + 1);
            s = reinterpret_cast<const uint4*>(WAh + (size_t)crow * 256 + k0 + chal);
            *reinterpret_cast<uint4*>(&Bh[crow][chal])     = __ldg(s);
            *reinterpret_cast<uint4*>(&Bh[crow][chal + 8]) = __ldg(s + 1);
            s = reinterpret_cast<const uint4*>(WAl + (size_t)crow * 256 + k0 + chal);
            *reinterpret_cast<uint4*>(&Bl[crow][chal])     = __ldg(s);
            *reinterpret_cast<uint4*>(&Bl[crow][chal + 8]) = __ldg(s + 1);
        }
        __syncthreads();
#pragma unroll
        for (int s = 0; s < 2; ++s) {             // 2 ksteps of 16
            const int kb = s * 16 + tig * 2;
            uint32_t fah[4][4], fal[4][4], fbh[4][2], fbl[4][2];
#pragma unroll
            for (int fm = 0; fm < 4; ++fm) {
                int r = wm * 64 + fm * 16 + gid;
                fah[fm][0] = *reinterpret_cast<const uint32_t*>(&Ah[r][kb]);
                fah[fm][1] = *reinterpret_cast<const uint32_t*>(&Ah[r + 8][kb]);
                fah[fm][2] = *reinterpret_cast<const uint32_t*>(&Ah[r][kb + 8]);
                fah[fm][3] = *reinterpret_cast<const uint32_t*>(&Ah[r + 8][kb + 8]);
                fal[fm][0] = *reinterpret_cast<const uint32_t*>(&Al[r][kb]);
                fal[fm][1] = *reinterpret_cast<const uint32_t*>(&Al[r + 8][kb]);
                fal[fm][2] = *reinterpret_cast<const uint32_t*>(&Al[r][kb + 8]);
                fal[fm][3] = *reinterpret_cast<const uint32_t*>(&Al[r + 8][kb + 8]);
            }
#pragma unroll
            for (int fn = 0; fn < 4; ++fn) {
                int n = wn * 32 + fn * 8 + gid;
                fbh[fn][0] = *reinterpret_cast<const uint32_t*>(&Bh[n][kb]);
                fbh[fn][1] = *reinterpret_cast<const uint32_t*>(&Bh[n][kb + 8]);
                fbl[fn][0] = *reinterpret_cast<const uint32_t*>(&Bl[n][kb]);
                fbl[fn][1] = *reinterpret_cast<const uint32_t*>(&Bl[n][kb + 8]);
            }
#pragma unroll
            for (int fm = 0; fm < 4; ++fm)
#pragma unroll
                for (int fn = 0; fn < 4; ++fn) {
                    mma16816(acc[fm][fn], fah[fm], fbh[fn]);
                    mma16816(acc[fm][fn], fah[fm], fbl[fn]);
                    mma16816(acc[fm][fn], fal[fm], fbh[fn]);
                }
        }
        __syncthreads();
    }

    // Epilogue: acc[fm][fn][{c0,c1 @row gid; c2,c3 @row gid+8}], cols tig*2..+1
    const int g0 = 2 * j;
#pragma unroll
    for (int fm = 0; fm < 4; ++fm) {
        int rbase = m0 + wm * 64 + fm * 16 + gid;
#pragma unroll
        for (int half = 0; half < 2; ++half) {
            int m = rbase + half * 8;
            if (m >= Nn) continue;
            size_t rowb = (size_t)m * H;
#pragma unroll
            for (int fn = 0; fn < 4; ++fn) {
                int c = wn * 32 + fn * 8 + tig * 2;
                float bias0 = __ldg(bl + g0 * H + c)     + __ldg(bl + (g0 + 1) * H + c);
                float bias1 = __ldg(bl + g0 * H + c + 1) + __ldg(bl + (g0 + 1) * H + c + 1);
                float v0 = acc[fm][fn][half * 2 + 0] + bias0;
                float v1 = acc[fm][fn][half * 2 + 1] + bias1;
                if (j == 0) {
                    float2 o = make_float2(sigmoidf_(v0), sigmoidf_(v1));
                    *reinterpret_cast<float2*>(g_z + rowb + c) = o;
                } else if (j == 1) {
                    float2 hv = *reinterpret_cast<const float2*>(hl + rowb + c);
                    float2 o = make_float2(sigmoidf_(v0) * hv.x, sigmoidf_(v1) * hv.y);
                    *reinterpret_cast<float2*>(g_rh + rowb + c) = o;
                } else {
                    *reinterpret_cast<float2*>(g_hx + rowb + c) = make_float2(v0, v1);
                }
            }
        }
    }
}

// ======================= mma.sync GEMM C ===================================
__global__ __launch_bounds__(256)
void gemmC_mma(const float* __restrict__ hl, int layer,
               float* __restrict__ out, int Nn) {
    __shared__ __nv_bfloat16 Ah[128][SST], Al[128][SST];
    __shared__ __nv_bfloat16 Bh[128][SST], Bl[128][SST];

    const int tid  = threadIdx.x;
    const int wid  = tid >> 5;
    const int lane = tid & 31;
    const int gid  = lane >> 2;
    const int tig  = lane & 3;
    const int wm   = wid & 1;
    const int wn   = wid >> 1;
    const int m0   = blockIdx.x * 128;

    const __nv_bfloat16* WCh = g_WCh + (size_t)layer * 128 * 128;
    const __nv_bfloat16* WCl = g_WCl + (size_t)layer * 128 * 128;

    const int crow = tid >> 1;
    const int chal = (tid & 1) * 16;

    float acc[4][4][4];
#pragma unroll
    for (int a = 0; a < 4; a++)
#pragma unroll
        for (int b = 0; b < 4; b++)
#pragma unroll
            for (int c = 0; c < 4; c++) acc[a][b][c] = 0.f;

    for (int kc = 0; kc < 4; ++kc) {        // K = 128, BK = 32
        const int k0 = kc * 32;
        {
            const uint4* s = reinterpret_cast<const uint4*>(
                g_arh_h + (size_t)(m0 + crow) * 128 + k0 + chal);
            *reinterpret_cast<uint4*>(&Ah[crow][chal])     = __ldg(s);
            *reinterpret_cast<uint4*>(&Ah[crow][chal + 8]) = __ldg(s + 1);
            s = reinterpret_cast<const uint4*>(
                g_arh_l + (size_t)(m0 + crow) * 128 + k0 + chal);
            *reinterpret_cast<uint4*>(&Al[crow][chal])     = __ldg(s);
            *reinterpret_cast<uint4*>(&Al[crow][chal + 8]) = __ldg(s + 1);
            s = reinterpret_cast<const uint4*>(WCh + (size_t)crow * 128 + k0 + chal);
            *reinterpret_cast<uint4*>(&Bh[crow][chal])     = __ldg(s);
            *reinterpret_cast<uint4*>(&Bh[crow][chal + 8]) = __ldg(s + 1);
            s = reinterpret_cast<const uint4*>(WCl + (size_t)crow * 128 + k0 + chal);
            *reinterpret_cast<uint4*>(&Bl[crow][chal])     = __ldg(s);
            *reinterpret_cast<uint4*>(&Bl[crow][chal + 8]) = __ldg(s + 1);
        }
        __syncthreads();
#pragma unroll
        for (int s = 0; s < 2; ++s) {
            const int kb = s * 16 + tig * 2;
            uint32_t fah[4][4], fal[4][4], fbh[4][2], fbl[4][2];
#pragma unroll
            for (int fm = 0; fm < 4; ++fm) {
                int r = wm * 64 + fm * 16 + gid;
                fah[fm][0] = *reinterpret_cast<const uint32_t*>(&Ah[r][kb]);
                fah[fm][1] = *reinterpret_cast<const uint32_t*>(&Ah[r + 8][kb]);
                fah[fm][2] = *reinterpret_cast<const uint32_t*>(&Ah[r][kb + 8]);
                fah[fm][3] = *reinterpret_cast<const uint32_t*>(&Ah[r + 8][kb + 8]);
                fal[fm][0] = *reinterpret_cast<const uint32_t*>(&Al[r][kb]);
                fal[fm][1] = *reinterpret_cast<const uint32_t*>(&Al[r + 8][kb]);
                fal[fm][2] = *reinterpret_cast<const uint32_t*>(&Al[r][kb + 8]);
                fal[fm][3] = *reinterpret_cast<const uint32_t*>(&Al[r + 8][kb + 8]);
            }
#pragma unroll
            for (int fn = 0; fn < 4; ++fn) {
                int n = wn * 32 + fn * 8 + gid;
                fbh[fn][0] = *reinterpret_cast<const uint32_t*>(&Bh[n][kb]);
                fbh[fn][1] = *reinterpret_cast<const uint32_t*>(&Bh[n][kb + 8]);
                fbl[fn][0] = *reinterpret_cast<const uint32_t*>(&Bl[n][kb]);
                fbl[fn][1] = *reinterpret_cast<const uint32_t*>(&Bl[n][kb + 8]);
            }
#pragma unroll
            for (int fm = 0; fm < 4; ++fm)
#pragma unroll
                for (int fn = 0; fn < 4; ++fn) {
                    mma16816(acc[fm][fn], fah[fm], fbh[fn]);
                    mma16816(acc[fm][fn], fah[fm], fbl[fn]);
                    mma16816(acc[fm][fn], fal[fm], fbh[fn]);
                }
        }
        __syncthreads();
    }

    // Epilogue: out = z*h + (1-z)*tanh(v + hx)
#pragma unroll
    for (int fm = 0; fm < 4; ++fm) {
        int rbase = m0 + wm * 64 + fm * 16 + gid;
#pragma unroll
        for (int half = 0; half < 2; ++half) {
            int m = rbase + half * 8;
            if (m >= Nn) continue;
            size_t rowb = (size_t)m * H;
#pragma unroll
            for (int fn = 0; fn < 4; ++fn) {
                int c = wn * 32 + fn * 8 + tig * 2;
                float2 hx = *reinterpret_cast<const float2*>(g_hx + rowb + c);
                float2 zz = *reinterpret_cast<const float2*>(g_z + rowb + c);
                float2 hv = *reinterpret_cast<const float2*>(hl + rowb + c);
                float v0 = acc[fm][fn][half * 2 + 0] + hx.x;
                float v1 = acc[fm][fn][half * 2 + 1] + hx.y;
                float2 o;
                o.x = zz.x * hv.x + (1.f - zz.x) * tanhf(v0);
                o.y = zz.y * hv.y + (1.f - zz.y) * tanhf(v1);
                *reinterpret_cast<float2*>(out + rowb + c) = o;
            }
        }
    }
}

// ======================= launch ============================================
extern "C" void kernel_launch(void* const* d_in, const int* in_sizes, int n_in,
                              void* d_out, int out_size) {
    const float* inp = (const float*)d_in[0];
    const int*   edg = (const int*)  d_in[1];
    const float* h   = (const float*)d_in[2];
    const float* W   = (const float*)d_in[3];
    const float* b   = (const float*)d_in[4];
    float* out = (float*)d_out;

    const int Nn = in_sizes[0] / H;          // 50000
    const int E  = in_sizes[1] / 2;          // 1,600,000
    const int L  = in_sizes[2] / (Nn * H);   // 2

    const int* src = edg;
    const int* dst = edg + E;

    const int eblocks = (E + 255) / 256;
    const int nblocks = (Nn + 255) / 256;
    const int gblocks = (Nn * 32 + 255) / 256;
    const int mblocks = (Nn + 127) / 128;    // 391

    // CSR build + weight pre-split — once per call
    csr_zero_kernel<<<nblocks, 256>>>(Nn);
    csr_hist_kernel<<<eblocks, 256>>>(dst, E);
    const int totW = L * 3 * 128 * 256 + L * 128 * 128;
    prep_w_kernel<<<(totW + 255) / 256, 256>>>(W, L);
    csr_scan_kernel<<<1, 1024>>>(Nn);
    csr_fill_kernel<<<eblocks, 256>>>(src, dst, E);

    for (int i = 0; i < L; i++) {
        const float* x  = (i == 0) ? inp : out + (size_t)(i - 1) * Nn * H;
        const float* hl = h + (size_t)i * Nn * H;
        const float* bl = b + (size_t)i * 6 * H;
        float* outl = out + (size_t)i * Nn * H;

        gather_xh_kernel<<<gblocks, 256>>>(x, hl, Nn);
        gemmA_mma<<<dim3(mblocks, 3), 256>>>(hl, bl, i, Nn);
        gather_rh_kernel<<<gblocks, 256>>>(Nn);
        gemmC_mma<<<mblocks, 256>>>(hl, i, outl, Nn);
    }
}

// round 10
// speedup vs baseline: 2.1816x; 1.5407x over previous
#include <cuda_runtime.h>
#include <cuda_bf16.h>
#include <math.h>
#include <stdint.h>

// Problem constants (Graph_GRU_84576495993467): N=50000, H=128, L=2, E=1.6M
constexpr int H = 128;
constexpr int NNMAX = 50048;          // 391 * 128 exactly
constexpr int EMAX  = 1605632;
constexpr int LMAX  = 2;

// Scratch (device globals; allocation-free). Zero-initialized at module load.
__device__ __nv_bfloat16 g_axh_h[NNMAX * 256];  // split [ax|ah], hi
__device__ __nv_bfloat16 g_axh_l[NNMAX * 256];  // split [ax|ah], lo
__device__ __nv_bfloat16 g_arh_h[NNMAX * H];
__device__ __nv_bfloat16 g_arh_l[NNMAX * H];
__device__ float g_z   [NNMAX * H];
__device__ float g_rh  [NNMAX * H];
__device__ float g_hx  [NNMAX * H];
__device__ int   g_cnt   [NNMAX];     // invariant: zero at entry of every call
__device__ int   g_rowptr[NNMAX + 1];
__device__ int   g_cursor[NNMAX];
__device__ int   g_col   [EMAX];
__device__ int   g_bsum  [256];
// Pre-split weights, [N,K] layout for mma B operand (row.col => B col-major)
__device__ __nv_bfloat16 g_WAh[LMAX * 3 * 128 * 256];
__device__ __nv_bfloat16 g_WAl[LMAX * 3 * 128 * 256];
__device__ __nv_bfloat16 g_WCh[LMAX * 128 * 128];
__device__ __nv_bfloat16 g_WCl[LMAX * 128 * 128];

__device__ __forceinline__ float4 f4add(float4 a, float4 b) {
    return make_float4(a.x + b.x, a.y + b.y, a.z + b.z, a.w + b.w);
}
__device__ __forceinline__ float sigmoidf_(float v) {
    return 1.0f / (1.0f + __expf(-v));
}
__device__ __forceinline__ uint32_t pk(__nv_bfloat16 a, __nv_bfloat16 b) {
    __nv_bfloat162 t; t.x = a; t.y = b;
    return *reinterpret_cast<uint32_t*>(&t);
}
// Split float4 into hi/lo bf16 packed pairs.
__device__ __forceinline__ void split4(float4 v, uint2& hi, uint2& lo) {
    __nv_bfloat16 h0 = __float2bfloat16_rn(v.x);
    __nv_bfloat16 h1 = __float2bfloat16_rn(v.y);
    __nv_bfloat16 h2 = __float2bfloat16_rn(v.z);
    __nv_bfloat16 h3 = __float2bfloat16_rn(v.w);
    hi = make_uint2(pk(h0, h1), pk(h2, h3));
    lo = make_uint2(pk(__float2bfloat16_rn(v.x - __bfloat162float(h0)),
                       __float2bfloat16_rn(v.y - __bfloat162float(h1))),
                    pk(__float2bfloat16_rn(v.z - __bfloat162float(h2)),
                       __float2bfloat16_rn(v.w - __bfloat162float(h3))));
}

// mma.sync m16n8k16 bf16 -> f32, D += A*B
__device__ __forceinline__ void mma16816(float* d, const uint32_t* a, const uint32_t* b) {
    asm volatile(
        "mma.sync.aligned.m16n8k16.row.col.f32.bf16.bf16.f32 "
        "{%0,%1,%2,%3}, {%4,%5,%6,%7}, {%8,%9}, {%0,%1,%2,%3};"
        : "+f"(d[0]), "+f"(d[1]), "+f"(d[2]), "+f"(d[3])
        : "r"(a[0]), "r"(a[1]), "r"(a[2]), "r"(a[3]), "r"(b[0]), "r"(b[1]));
}

// ======================= CSR build =========================================
__global__ void csr_hist_kernel(const int* __restrict__ dst, int E) {
    int i = blockIdx.x * blockDim.x + threadIdx.x;
    if (i < E) atomicAdd(&g_cnt[__ldg(dst + i)], 1);
}

// Pass 1: per-block inclusive scan over 256 counts; write local-exclusive
// prefixes into rowptr and the block total into g_bsum.
__global__ __launch_bounds__(256)
void csr_scan1(int Nn) {
    __shared__ int sc[256];
    const int t = threadIdx.x;
    const int i = blockIdx.x * 256 + t;
    int c = (i < Nn) ? g_cnt[i] : 0;
    sc[t] = c;
    __syncthreads();
#pragma unroll
    for (int d = 1; d < 256; d <<= 1) {
        int v = sc[t];
        int vd = (t >= d) ? sc[t - d] : 0;
        __syncthreads();
        sc[t] = v + vd;
        __syncthreads();
    }
    if (i < Nn) g_rowptr[i] = sc[t] - c;   // exclusive within block
    if (t == 255) g_bsum[blockIdx.x] = sc[255];
}

// Pass 2: every block redundantly scans the <=256 block sums, then applies
// its own offset and initializes the cursor. rowptr[Nn] = E.
__global__ __launch_bounds__(256)
void csr_scan2(int Nn, int E, int nb) {
    __shared__ int sb[256];
    const int t = threadIdx.x;
    sb[t] = (t < nb) ? g_bsum[t] : 0;
    __syncthreads();
#pragma unroll
    for (int d = 1; d < 256; d <<= 1) {
        int v = sb[t];
        int vd = (t >= d) ? sb[t - d] : 0;
        __syncthreads();
        sb[t] = v + vd;
        __syncthreads();
    }
    const int off = (blockIdx.x > 0) ? sb[blockIdx.x - 1] : 0;
    const int i = blockIdx.x * 256 + t;
    if (i < Nn) {
        int r = g_rowptr[i] + off;
        g_rowptr[i] = r;
        g_cursor[i] = r;
    }
    if (i == 0) g_rowptr[Nn] = E;
}

__global__ void csr_fill_kernel(const int* __restrict__ src,
                                const int* __restrict__ dst, int E) {
    int i = blockIdx.x * blockDim.x + threadIdx.x;
    if (i < E) {
        int d = __ldg(dst + i);
        int pos = atomicAdd(&g_cursor[d], 1);
        g_col[pos] = __ldg(src + i);
    }
}

// Restore the "g_cnt is zero" invariant for the next call (graph replays).
__global__ void csr_rezero(int Nn) {
    int i = blockIdx.x * blockDim.x + threadIdx.x;
    if (i < Nn) g_cnt[i] = 0;
}

// ======================= Weight pre-split ==================================
__global__ void prep_w_kernel(const float* __restrict__ W, int L) {
    int i = blockIdx.x * blockDim.x + threadIdx.x;
    const int totA = L * 3 * 128 * 256;
    const int totC = L * 128 * 128;
    if (i < totA) {
        int k = i & 255;
        int t = i >> 8;
        int n = t & 127;
        t >>= 7;
        int j = t % 3;
        int l = t / 3;
        int gsel = (k < 128) ? 2 * j : 2 * j + 1;
        int kk = k & 127;
        float v = __ldg(W + (((size_t)l * 6 + gsel) * 128 + kk) * 128 + n);
        __nv_bfloat16 hv = __float2bfloat16_rn(v);
        g_WAh[i] = hv;
        g_WAl[i] = __float2bfloat16_rn(v - __bfloat162float(hv));
    } else if (i < totA + totC) {
        int q = i - totA;
        int k = q & 127;
        int t = q >> 7;
        int n = t & 127;
        int l = t >> 7;
        float v = __ldg(W + (((size_t)l * 6 + 5) * 128 + k) * 128 + n);
        __nv_bfloat16 hv = __float2bfloat16_rn(v);
        g_WCh[q] = hv;
        g_WCl[q] = __float2bfloat16_rn(v - __bfloat162float(hv));
    }
}

// ======================= Gather kernels (emit split bf16) ==================
__global__ __launch_bounds__(256)
void gather_xh_kernel(const float* __restrict__ x,
                      const float* __restrict__ hl, int Nn) {
    int w = (blockIdx.x * blockDim.x + threadIdx.x) >> 5;
    if (w >= Nn) return;
    const int lane = threadIdx.x & 31;
    const int off = lane << 2;
    const int start = __ldg(g_rowptr + w);
    const int end   = __ldg(g_rowptr + w + 1);

    float4 ax = __ldg(reinterpret_cast<const float4*>(x  + (size_t)w * H + off));
    float4 ah = __ldg(reinterpret_cast<const float4*>(hl + (size_t)w * H + off));

    for (int j = start; j < end; j += 32) {
        int rem = end - j;
        int idx = (lane < rem) ? __ldg(g_col + j + lane) : 0;
        int m = min(rem, 32);
#pragma unroll 4
        for (int k = 0; k < m; ++k) {
            int s = __shfl_sync(0xffffffffu, idx, k);
            ax = f4add(ax, __ldg(reinterpret_cast<const float4*>(x  + (size_t)s * H + off)));
            ah = f4add(ah, __ldg(reinterpret_cast<const float4*>(hl + (size_t)s * H + off)));
        }
    }
    uint2 hi, lo;
    split4(ax, hi, lo);
    *reinterpret_cast<uint2*>(g_axh_h + (size_t)w * 256 + off) = hi;
    *reinterpret_cast<uint2*>(g_axh_l + (size_t)w * 256 + off) = lo;
    split4(ah, hi, lo);
    *reinterpret_cast<uint2*>(g_axh_h + (size_t)w * 256 + 128 + off) = hi;
    *reinterpret_cast<uint2*>(g_axh_l + (size_t)w * 256 + 128 + off) = lo;
}

__global__ __launch_bounds__(256)
void gather_rh_kernel(int Nn) {
    int w = (blockIdx.x * blockDim.x + threadIdx.x) >> 5;
    if (w >= Nn) return;
    const int lane = threadIdx.x & 31;
    const int off = lane << 2;
    const int start = __ldg(g_rowptr + w);
    const int end   = __ldg(g_rowptr + w + 1);

    float4 a = *reinterpret_cast<const float4*>(g_rh + (size_t)w * H + off);

    for (int j = start; j < end; j += 32) {
        int rem = end - j;
        int idx = (lane < rem) ? __ldg(g_col + j + lane) : 0;
        int m = min(rem, 32);
#pragma unroll 4
        for (int k = 0; k < m; ++k) {
            int s = __shfl_sync(0xffffffffu, idx, k);
            a = f4add(a, *reinterpret_cast<const float4*>(g_rh + (size_t)s * H + off));
        }
    }
    uint2 hi, lo;
    split4(a, hi, lo);
    *reinterpret_cast<uint2*>(g_arh_h + (size_t)w * H + off) = hi;
    *reinterpret_cast<uint2*>(g_arh_l + (size_t)w * H + off) = lo;
}

// ======================= mma.sync GEMM A ===================================
// CTA: 128 rows x 128 cols (one gate, blockIdx.y = j). 8 warps, each 64x32.
// Split-bf16: D = Ah*Bh + Ah*Bl + Al*Bh  (fp32 accumulate).
constexpr int SST = 40;

__global__ __launch_bounds__(256)
void gemmA_mma(const float* __restrict__ hl, const float* __restrict__ bl,
               int layer, int Nn) {
    __shared__ __nv_bfloat16 Ah[128][SST], Al[128][SST];
    __shared__ __nv_bfloat16 Bh[128][SST], Bl[128][SST];

    const int tid  = threadIdx.x;
    const int wid  = tid >> 5;
    const int lane = tid & 31;
    const int gid  = lane >> 2;
    const int tig  = lane & 3;
    const int wm   = wid & 1;          // 2 M-warps (64 rows each)
    const int wn   = wid >> 1;         // 4 N-warps (32 cols each)
    const int j    = blockIdx.y;
    const int m0   = blockIdx.x * 128;
    const int nchunks = (j == 2) ? 4 : 8;   // K = 128 or 256, BK = 32

    const __nv_bfloat16* WAh = g_WAh + ((size_t)layer * 3 + j) * 128 * 256;
    const __nv_bfloat16* WAl = g_WAl + ((size_t)layer * 3 + j) * 128 * 256;

    const int crow = tid >> 1;          // copy: row 0..127
    const int chal = (tid & 1) * 16;    // copy: 16-col half

    float acc[4][4][4];
#pragma unroll
    for (int a = 0; a < 4; a++)
#pragma unroll
        for (int b = 0; b < 4; b++)
#pragma unroll
            for (int c = 0; c < 4; c++) acc[a][b][c] = 0.f;

    for (int kc = 0; kc < nchunks; ++kc) {
        const int k0 = kc * 32;
        {
            const uint4* s = reinterpret_cast<const uint4*>(
                g_axh_h + (size_t)(m0 + crow) * 256 + k0 + chal);
            *reinterpret_cast<uint4*>(&Ah[crow][chal])     = __ldg(s);
            *reinterpret_cast<uint4*>(&Ah[crow][chal + 8]) = __ldg(s + 1);
            s = reinterpret_cast<const uint4*>(
                g_axh_l + (size_t)(m0 + crow) * 256 + k0 + chal);
            *reinterpret_cast<uint4*>(&Al[crow][chal])     = __ldg(s);
            *reinterpret_cast<uint4*>(&Al[crow][chal + 8]) = __ldg(s + 1);
            s = reinterpret_cast<const uint4*>(WAh + (size_t)crow * 256 + k0 + chal);
            *reinterpret_cast<uint4*>(&Bh[crow][chal])     = __ldg(s);
            *reinterpret_cast<uint4*>(&Bh[crow][chal + 8]) = __ldg(s + 1);
            s = reinterpret_cast<const uint4*>(WAl + (size_t)crow * 256 + k0 + chal);
            *reinterpret_cast<uint4*>(&Bl[crow][chal])     = __ldg(s);
            *reinterpret_cast<uint4*>(&Bl[crow][chal + 8]) = __ldg(s + 1);
        }
        __syncthreads();
#pragma unroll
        for (int s = 0; s < 2; ++s) {             // 2 ksteps of 16
            const int kb = s * 16 + tig * 2;
            uint32_t fah[4][4], fal[4][4], fbh[4][2], fbl[4][2];
#pragma unroll
            for (int fm = 0; fm < 4; ++fm) {
                int r = wm * 64 + fm * 16 + gid;
                fah[fm][0] = *reinterpret_cast<const uint32_t*>(&Ah[r][kb]);
                fah[fm][1] = *reinterpret_cast<const uint32_t*>(&Ah[r + 8][kb]);
                fah[fm][2] = *reinterpret_cast<const uint32_t*>(&Ah[r][kb + 8]);
                fah[fm][3] = *reinterpret_cast<const uint32_t*>(&Ah[r + 8][kb + 8]);
                fal[fm][0] = *reinterpret_cast<const uint32_t*>(&Al[r][kb]);
                fal[fm][1] = *reinterpret_cast<const uint32_t*>(&Al[r + 8][kb]);
                fal[fm][2] = *reinterpret_cast<const uint32_t*>(&Al[r][kb + 8]);
                fal[fm][3] = *reinterpret_cast<const uint32_t*>(&Al[r + 8][kb + 8]);
            }
#pragma unroll
            for (int fn = 0; fn < 4; ++fn) {
                int n = wn * 32 + fn * 8 + gid;
                fbh[fn][0] = *reinterpret_cast<const uint32_t*>(&Bh[n][kb]);
                fbh[fn][1] = *reinterpret_cast<const uint32_t*>(&Bh[n][kb + 8]);
                fbl[fn][0] = *reinterpret_cast<const uint32_t*>(&Bl[n][kb]);
                fbl[fn][1] = *reinterpret_cast<const uint32_t*>(&Bl[n][kb + 8]);
            }
#pragma unroll
            for (int fm = 0; fm < 4; ++fm)
#pragma unroll
                for (int fn = 0; fn < 4; ++fn) {
                    mma16816(acc[fm][fn], fah[fm], fbh[fn]);
                    mma16816(acc[fm][fn], fah[fm], fbl[fn]);
                    mma16816(acc[fm][fn], fal[fm], fbh[fn]);
                }
        }
        __syncthreads();
    }

    // Epilogue: acc[fm][fn][{c0,c1 @row gid; c2,c3 @row gid+8}], cols tig*2..+1
    const int g0 = 2 * j;
#pragma unroll
    for (int fm = 0; fm < 4; ++fm) {
        int rbase = m0 + wm * 64 + fm * 16 + gid;
#pragma unroll
        for (int half = 0; half < 2; ++half) {
            int m = rbase + half * 8;
            if (m >= Nn) continue;
            size_t rowb = (size_t)m * H;
#pragma unroll
            for (int fn = 0; fn < 4; ++fn) {
                int c = wn * 32 + fn * 8 + tig * 2;
                float bias0 = __ldg(bl + g0 * H + c)     + __ldg(bl + (g0 + 1) * H + c);
                float bias1 = __ldg(bl + g0 * H + c + 1) + __ldg(bl + (g0 + 1) * H + c + 1);
                float v0 = acc[fm][fn][half * 2 + 0] + bias0;
                float v1 = acc[fm][fn][half * 2 + 1] + bias1;
                if (j == 0) {
                    float2 o = make_float2(sigmoidf_(v0), sigmoidf_(v1));
                    *reinterpret_cast<float2*>(g_z + rowb + c) = o;
                } else if (j == 1) {
                    float2 hv = *reinterpret_cast<const float2*>(hl + rowb + c);
                    float2 o = make_float2(sigmoidf_(v0) * hv.x, sigmoidf_(v1) * hv.y);
                    *reinterpret_cast<float2*>(g_rh + rowb + c) = o;
                } else {
                    *reinterpret_cast<float2*>(g_hx + rowb + c) = make_float2(v0, v1);
                }
            }
        }
    }
}

// ======================= mma.sync GEMM C ===================================
__global__ __launch_bounds__(256)
void gemmC_mma(const float* __restrict__ hl, int layer,
               float* __restrict__ out, int Nn) {
    __shared__ __nv_bfloat16 Ah[128][SST], Al[128][SST];
    __shared__ __nv_bfloat16 Bh[128][SST], Bl[128][SST];

    const int tid  = threadIdx.x;
    const int wid  = tid >> 5;
    const int lane = tid & 31;
    const int gid  = lane >> 2;
    const int tig  = lane & 3;
    const int wm   = wid & 1;
    const int wn   = wid >> 1;
    const int m0   = blockIdx.x * 128;

    const __nv_bfloat16* WCh = g_WCh + (size_t)layer * 128 * 128;
    const __nv_bfloat16* WCl = g_WCl + (size_t)layer * 128 * 128;

    const int crow = tid >> 1;
    const int chal = (tid & 1) * 16;

    float acc[4][4][4];
#pragma unroll
    for (int a = 0; a < 4; a++)
#pragma unroll
        for (int b = 0; b < 4; b++)
#pragma unroll
            for (int c = 0; c < 4; c++) acc[a][b][c] = 0.f;

    for (int kc = 0; kc < 4; ++kc) {        // K = 128, BK = 32
        const int k0 = kc * 32;
        {
            const uint4* s = reinterpret_cast<const uint4*>(
                g_arh_h + (size_t)(m0 + crow) * 128 + k0 + chal);
            *reinterpret_cast<uint4*>(&Ah[crow][chal])     = __ldg(s);
            *reinterpret_cast<uint4*>(&Ah[crow][chal + 8]) = __ldg(s + 1);
            s = reinterpret_cast<const uint4*>(
                g_arh_l + (size_t)(m0 + crow) * 128 + k0 + chal);
            *reinterpret_cast<uint4*>(&Al[crow][chal])     = __ldg(s);
            *reinterpret_cast<uint4*>(&Al[crow][chal + 8]) = __ldg(s + 1);
            s = reinterpret_cast<const uint4*>(WCh + (size_t)crow * 128 + k0 + chal);
            *reinterpret_cast<uint4*>(&Bh[crow][chal])     = __ldg(s);
            *reinterpret_cast<uint4*>(&Bh[crow][chal + 8]) = __ldg(s + 1);
            s = reinterpret_cast<const uint4*>(WCl + (size_t)crow * 128 + k0 + chal);
            *reinterpret_cast<uint4*>(&Bl[crow][chal])     = __ldg(s);
            *reinterpret_cast<uint4*>(&Bl[crow][chal + 8]) = __ldg(s + 1);
        }
        __syncthreads();
#pragma unroll
        for (int s = 0; s < 2; ++s) {
            const int kb = s * 16 + tig * 2;
            uint32_t fah[4][4], fal[4][4], fbh[4][2], fbl[4][2];
#pragma unroll
            for (int fm = 0; fm < 4; ++fm) {
                int r = wm * 64 + fm * 16 + gid;
                fah[fm][0] = *reinterpret_cast<const uint32_t*>(&Ah[r][kb]);
                fah[fm][1] = *reinterpret_cast<const uint32_t*>(&Ah[r + 8][kb]);
                fah[fm][2] = *reinterpret_cast<const uint32_t*>(&Ah[r][kb + 8]);
                fah[fm][3] = *reinterpret_cast<const uint32_t*>(&Ah[r + 8][kb + 8]);
                fal[fm][0] = *reinterpret_cast<const uint32_t*>(&Al[r][kb]);
                fal[fm][1] = *reinterpret_cast<const uint32_t*>(&Al[r + 8][kb]);
                fal[fm][2] = *reinterpret_cast<const uint32_t*>(&Al[r][kb + 8]);
                fal[fm][3] = *reinterpret_cast<const uint32_t*>(&Al[r + 8][kb + 8]);
            }
#pragma unroll
            for (int fn = 0; fn < 4; ++fn) {
                int n = wn * 32 + fn * 8 + gid;
                fbh[fn][0] = *reinterpret_cast<const uint32_t*>(&Bh[n][kb]);
                fbh[fn][1] = *reinterpret_cast<const uint32_t*>(&Bh[n][kb + 8]);
                fbl[fn][0] = *reinterpret_cast<const uint32_t*>(&Bl[n][kb]);
                fbl[fn][1] = *reinterpret_cast<const uint32_t*>(&Bl[n][kb + 8]);
            }
#pragma unroll
            for (int fm = 0; fm < 4; ++fm)
#pragma unroll
                for (int fn = 0; fn < 4; ++fn) {
                    mma16816(acc[fm][fn], fah[fm], fbh[fn]);
                    mma16816(acc[fm][fn], fah[fm], fbl[fn]);
                    mma16816(acc[fm][fn], fal[fm], fbh[fn]);
                }
        }
        __syncthreads();
    }

    // Epilogue: out = z*h + (1-z)*tanh(v + hx)
#pragma unroll
    for (int fm = 0; fm < 4; ++fm) {
        int rbase = m0 + wm * 64 + fm * 16 + gid;
#pragma unroll
        for (int half = 0; half < 2; ++half) {
            int m = rbase + half * 8;
            if (m >= Nn) continue;
            size_t rowb = (size_t)m * H;
#pragma unroll
            for (int fn = 0; fn < 4; ++fn) {
                int c = wn * 32 + fn * 8 + tig * 2;
                float2 hx = *reinterpret_cast<const float2*>(g_hx + rowb + c);
                float2 zz = *reinterpret_cast<const float2*>(g_z + rowb + c);
                float2 hv = *reinterpret_cast<const float2*>(hl + rowb + c);
                float v0 = acc[fm][fn][half * 2 + 0] + hx.x;
                float v1 = acc[fm][fn][half * 2 + 1] + hx.y;
                float2 o;
                o.x = zz.x * hv.x + (1.f - zz.x) * tanhf(v0);
                o.y = zz.y * hv.y + (1.f - zz.y) * tanhf(v1);
                *reinterpret_cast<float2*>(out + rowb + c) = o;
            }
        }
    }
}

// ======================= launch ============================================
extern "C" void kernel_launch(void* const* d_in, const int* in_sizes, int n_in,
                              void* d_out, int out_size) {
    const float* inp = (const float*)d_in[0];
    const int*   edg = (const int*)  d_in[1];
    const float* h   = (const float*)d_in[2];
    const float* W   = (const float*)d_in[3];
    const float* b   = (const float*)d_in[4];
    float* out = (float*)d_out;

    const int Nn = in_sizes[0] / H;          // 50000
    const int E  = in_sizes[1] / 2;          // 1,600,000
    const int L  = in_sizes[2] / (Nn * H);   // 2

    const int* src = edg;
    const int* dst = edg + E;

    const int eblocks = (E + 255) / 256;
    const int nblocks = (Nn + 255) / 256;    // 196
    const int gblocks = (Nn * 32 + 255) / 256;
    const int mblocks = (Nn + 127) / 128;    // 391

    // CSR build (g_cnt is zero on entry: module-load init + trailing rezero).
    csr_hist_kernel<<<eblocks, 256>>>(dst, E);
    csr_scan1<<<nblocks, 256>>>(Nn);
    csr_scan2<<<nblocks, 256>>>(Nn, E, nblocks);
    csr_fill_kernel<<<eblocks, 256>>>(src, dst, E);
    const int totW = L * 3 * 128 * 256 + L * 128 * 128;
    prep_w_kernel<<<(totW + 255) / 256, 256>>>(W, L);

    for (int i = 0; i < L; i++) {
        const float* x  = (i == 0) ? inp : out + (size_t)(i - 1) * Nn * H;
        const float* hl = h + (size_t)i * Nn * H;
        const float* bl = b + (size_t)i * 6 * H;
        float* outl = out + (size_t)i * Nn * H;

        gather_xh_kernel<<<gblocks, 256>>>(x, hl, Nn);
        gemmA_mma<<<dim3(mblocks, 3), 256>>>(hl, bl, i, Nn);
        gather_rh_kernel<<<gblocks, 256>>>(Nn);
        gemmC_mma<<<mblocks, 256>>>(hl, i, outl, Nn);
    }

    // Restore invariant for next call.
    csr_rezero<<<nblocks, 256>>>(Nn);
}

// round 11
// speedup vs baseline: 2.1962x; 1.0067x over previous
#include <cuda_runtime.h>
#include <cuda_bf16.h>
#include <cuda_fp16.h>
#include <math.h>
#include <stdint.h>

// Problem constants (Graph_GRU_84576495993467): N=50000, H=128, L=2, E=1.6M
constexpr int H = 128;
constexpr int NNMAX = 50048;          // 391 * 128 exactly
constexpr int EMAX  = 1605632;
constexpr int LMAX  = 2;

// Scratch (device globals; allocation-free). Zero-initialized at module load.
__device__ __nv_bfloat16 g_axh_h[NNMAX * 256];  // split [ax|ah], hi
__device__ __nv_bfloat16 g_axh_l[NNMAX * 256];  // split [ax|ah], lo
__device__ __nv_bfloat16 g_arh_h[NNMAX * H];
__device__ __nv_bfloat16 g_arh_l[NNMAX * H];
__device__ float g_z   [NNMAX * H];
__device__ float g_rh  [NNMAX * H];
__device__ float g_hx  [NNMAX * H];
__device__ __half g_x16 [NNMAX * H];   // fp16 neighbor-gather copies
__device__ __half g_h16 [NNMAX * H];
__device__ __half g_rh16[NNMAX * H];
__device__ int   g_cnt   [NNMAX];     // invariant: zero at entry of every call
__device__ int   g_rowptr[NNMAX + 1];
__device__ int   g_cursor[NNMAX];
__device__ int   g_col   [EMAX];
__device__ int   g_bsum  [256];
// Pre-split weights, [N,K] layout for mma B operand (row.col => B col-major)
__device__ __nv_bfloat16 g_WAh[LMAX * 3 * 128 * 256];
__device__ __nv_bfloat16 g_WAl[LMAX * 3 * 128 * 256];
__device__ __nv_bfloat16 g_WCh[LMAX * 128 * 128];
__device__ __nv_bfloat16 g_WCl[LMAX * 128 * 128];

__device__ __forceinline__ float sigmoidf_(float v) {
    return 1.0f / (1.0f + __expf(-v));
}
__device__ __forceinline__ uint32_t pk(__nv_bfloat16 a, __nv_bfloat16 b) {
    __nv_bfloat162 t; t.x = a; t.y = b;
    return *reinterpret_cast<uint32_t*>(&t);
}
// Split float4 into hi/lo bf16 packed pairs.
__device__ __forceinline__ void split4(float4 v, uint2& hi, uint2& lo) {
    __nv_bfloat16 h0 = __float2bfloat16_rn(v.x);
    __nv_bfloat16 h1 = __float2bfloat16_rn(v.y);
    __nv_bfloat16 h2 = __float2bfloat16_rn(v.z);
    __nv_bfloat16 h3 = __float2bfloat16_rn(v.w);
    hi = make_uint2(pk(h0, h1), pk(h2, h3));
    lo = make_uint2(pk(__float2bfloat16_rn(v.x - __bfloat162float(h0)),
                       __float2bfloat16_rn(v.y - __bfloat162float(h1))),
                    pk(__float2bfloat16_rn(v.z - __bfloat162float(h2)),
                       __float2bfloat16_rn(v.w - __bfloat162float(h3))));
}
// Accumulate 4 halves (uint2) into float4.
__device__ __forceinline__ void acc_h4(float4& a, uint2 u) {
    __half2 p0 = *reinterpret_cast<__half2*>(&u.x);
    __half2 p1 = *reinterpret_cast<__half2*>(&u.y);
    float2 f0 = __half22float2(p0);
    float2 f1 = __half22float2(p1);
    a.x += f0.x; a.y += f0.y; a.z += f1.x; a.w += f1.y;
}
__device__ __forceinline__ uint2 pack_h4(float4 v) {
    __half2 p0 = __floats2half2_rn(v.x, v.y);
    __half2 p1 = __floats2half2_rn(v.z, v.w);
    return make_uint2(*reinterpret_cast<uint32_t*>(&p0),
                      *reinterpret_cast<uint32_t*>(&p1));
}

// mma.sync m16n8k16 bf16 -> f32, D += A*B
__device__ __forceinline__ void mma16816(float* d, const uint32_t* a, const uint32_t* b) {
    asm volatile(
        "mma.sync.aligned.m16n8k16.row.col.f32.bf16.bf16.f32 "
        "{%0,%1,%2,%3}, {%4,%5,%6,%7}, {%8,%9}, {%0,%1,%2,%3};"
        : "+f"(d[0]), "+f"(d[1]), "+f"(d[2]), "+f"(d[3])
        : "r"(a[0]), "r"(a[1]), "r"(a[2]), "r"(a[3]), "r"(b[0]), "r"(b[1]));
}

// ======================= CSR build =========================================
__global__ void csr_hist_kernel(const int* __restrict__ dst, int E) {
    int i = blockIdx.x * blockDim.x + threadIdx.x;
    if (i < E) atomicAdd(&g_cnt[__ldg(dst + i)], 1);
}

__global__ __launch_bounds__(256)
void csr_scan1(int Nn) {
    __shared__ int sc[256];
    const int t = threadIdx.x;
    const int i = blockIdx.x * 256 + t;
    int c = (i < Nn) ? g_cnt[i] : 0;
    sc[t] = c;
    __syncthreads();
#pragma unroll
    for (int d = 1; d < 256; d <<= 1) {
        int v = sc[t];
        int vd = (t >= d) ? sc[t - d] : 0;
        __syncthreads();
        sc[t] = v + vd;
        __syncthreads();
    }
    if (i < Nn) g_rowptr[i] = sc[t] - c;   // exclusive within block
    if (t == 255) g_bsum[blockIdx.x] = sc[255];
}

__global__ __launch_bounds__(256)
void csr_scan2(int Nn, int E, int nb) {
    __shared__ int sb[256];
    const int t = threadIdx.x;
    sb[t] = (t < nb) ? g_bsum[t] : 0;
    __syncthreads();
#pragma unroll
    for (int d = 1; d < 256; d <<= 1) {
        int v = sb[t];
        int vd = (t >= d) ? sb[t - d] : 0;
        __syncthreads();
        sb[t] = v + vd;
        __syncthreads();
    }
    const int off = (blockIdx.x > 0) ? sb[blockIdx.x - 1] : 0;
    const int i = blockIdx.x * 256 + t;
    if (i < Nn) {
        int r = g_rowptr[i] + off;
        g_rowptr[i] = r;
        g_cursor[i] = r;
    }
    if (i == 0) g_rowptr[Nn] = E;
}

__global__ void csr_fill_kernel(const int* __restrict__ src,
                                const int* __restrict__ dst, int E) {
    int i = blockIdx.x * blockDim.x + threadIdx.x;
    if (i < E) {
        int d = __ldg(dst + i);
        int pos = atomicAdd(&g_cursor[d], 1);
        g_col[pos] = __ldg(src + i);
    }
}

__global__ void csr_rezero(int Nn) {
    int i = blockIdx.x * blockDim.x + threadIdx.x;
    if (i < Nn) g_cnt[i] = 0;
}

// ======================= Weight pre-split ==================================
__global__ void prep_w_kernel(const float* __restrict__ W, int L) {
    int i = blockIdx.x * blockDim.x + threadIdx.x;
    const int totA = L * 3 * 128 * 256;
    const int totC = L * 128 * 128;
    if (i < totA) {
        int k = i & 255;
        int t = i >> 8;
        int n = t & 127;
        t >>= 7;
        int j = t % 3;
        int l = t / 3;
        int gsel = (k < 128) ? 2 * j : 2 * j + 1;
        int kk = k & 127;
        float v = __ldg(W + (((size_t)l * 6 + gsel) * 128 + kk) * 128 + n);
        __nv_bfloat16 hv = __float2bfloat16_rn(v);
        g_WAh[i] = hv;
        g_WAl[i] = __float2bfloat16_rn(v - __bfloat162float(hv));
    } else if (i < totA + totC) {
        int q = i - totA;
        int k = q & 127;
        int t = q >> 7;
        int n = t & 127;
        int l = t >> 7;
        float v = __ldg(W + (((size_t)l * 6 + 5) * 128 + k) * 128 + n);
        __nv_bfloat16 hv = __float2bfloat16_rn(v);
        g_WCh[q] = hv;
        g_WCl[q] = __float2bfloat16_rn(v - __bfloat162float(hv));
    }
}

// ======================= fp16 conversion (per layer) =======================
__global__ __launch_bounds__(256)
void cvt_xh_kernel(const float* __restrict__ x, const float* __restrict__ hl,
                   int n4) {
    int i = blockIdx.x * blockDim.x + threadIdx.x;
    if (i >= n4) return;
    float4 vx = __ldg(reinterpret_cast<const float4*>(x) + i);
    float4 vh = __ldg(reinterpret_cast<const float4*>(hl) + i);
    reinterpret_cast<uint2*>(g_x16)[i] = pack_h4(vx);
    reinterpret_cast<uint2*>(g_h16)[i] = pack_h4(vh);
}

// ======================= Gather kernels (fp16 neighbors) ===================
__global__ __launch_bounds__(256)
void gather_xh_kernel(const float* __restrict__ x,
                      const float* __restrict__ hl, int Nn) {
    int w = (blockIdx.x * blockDim.x + threadIdx.x) >> 5;
    if (w >= Nn) return;
    const int lane = threadIdx.x & 31;
    const int off = lane << 2;
    const int start = __ldg(g_rowptr + w);
    const int end   = __ldg(g_rowptr + w + 1);

    // self row in fp32
    float4 ax = __ldg(reinterpret_cast<const float4*>(x  + (size_t)w * H + off));
    float4 ah = __ldg(reinterpret_cast<const float4*>(hl + (size_t)w * H + off));

    for (int j = start; j < end; j += 32) {
        int rem = end - j;
        int idx = (lane < rem) ? __ldg(g_col + j + lane) : 0;
        int m = min(rem, 32);
#pragma unroll 4
        for (int k = 0; k < m; ++k) {
            int s = __shfl_sync(0xffffffffu, idx, k);
            acc_h4(ax, __ldg(reinterpret_cast<const uint2*>(g_x16 + (size_t)s * H + off)));
            acc_h4(ah, __ldg(reinterpret_cast<const uint2*>(g_h16 + (size_t)s * H + off)));
        }
    }
    uint2 hi, lo;
    split4(ax, hi, lo);
    *reinterpret_cast<uint2*>(g_axh_h + (size_t)w * 256 + off) = hi;
    *reinterpret_cast<uint2*>(g_axh_l + (size_t)w * 256 + off) = lo;
    split4(ah, hi, lo);
    *reinterpret_cast<uint2*>(g_axh_h + (size_t)w * 256 + 128 + off) = hi;
    *reinterpret_cast<uint2*>(g_axh_l + (size_t)w * 256 + 128 + off) = lo;
}

__global__ __launch_bounds__(256)
void gather_rh_kernel(int Nn) {
    int w = (blockIdx.x * blockDim.x + threadIdx.x) >> 5;
    if (w >= Nn) return;
    const int lane = threadIdx.x & 31;
    const int off = lane << 2;
    const int start = __ldg(g_rowptr + w);
    const int end   = __ldg(g_rowptr + w + 1);

    float4 a = *reinterpret_cast<const float4*>(g_rh + (size_t)w * H + off);

    for (int j = start; j < end; j += 32) {
        int rem = end - j;
        int idx = (lane < rem) ? __ldg(g_col + j + lane) : 0;
        int m = min(rem, 32);
#pragma unroll 4
        for (int k = 0; k < m; ++k) {
            int s = __shfl_sync(0xffffffffu, idx, k);
            acc_h4(a, __ldg(reinterpret_cast<const uint2*>(g_rh16 + (size_t)s * H + off)));
        }
    }
    uint2 hi, lo;
    split4(a, hi, lo);
    *reinterpret_cast<uint2*>(g_arh_h + (size_t)w * H + off) = hi;
    *reinterpret_cast<uint2*>(g_arh_l + (size_t)w * H + off) = lo;
}

// ======================= mma.sync GEMM A ===================================
// CTA: 128 rows x 128 cols (one gate, blockIdx.y = j). 8 warps, each 64x32.
// Split-bf16: D = Ah*Bh + Ah*Bl + Al*Bh  (fp32 accumulate).
constexpr int SST = 40;

__global__ __launch_bounds__(256)
void gemmA_mma(const float* __restrict__ hl, const float* __restrict__ bl,
               int layer, int Nn) {
    __shared__ __nv_bfloat16 Ah[128][SST], Al[128][SST];
    __shared__ __nv_bfloat16 Bh[128][SST], Bl[128][SST];

    const int tid  = threadIdx.x;
    const int wid  = tid >> 5;
    const int lane = tid & 31;
    const int gid  = lane >> 2;
    const int tig  = lane & 3;
    const int wm   = wid & 1;          // 2 M-warps (64 rows each)
    const int wn   = wid >> 1;         // 4 N-warps (32 cols each)
    const int j    = blockIdx.y;
    const int m0   = blockIdx.x * 128;
    const int nchunks = (j == 2) ? 4 : 8;   // K = 128 or 256, BK = 32

    const __nv_bfloat16* WAh = g_WAh + ((size_t)layer * 3 + j) * 128 * 256;
    const __nv_bfloat16* WAl = g_WAl + ((size_t)layer * 3 + j) * 128 * 256;

    const int crow = tid >> 1;          // copy: row 0..127
    const int chal = (tid & 1) * 16;    // copy: 16-col half

    float acc[4][4][4];
#pragma unroll
    for (int a = 0; a < 4; a++)
#pragma unroll
        for (int b = 0; b < 4; b++)
#pragma unroll
            for (int c = 0; c < 4; c++) acc[a][b][c] = 0.f;

    for (int kc = 0; kc < nchunks; ++kc) {
        const int k0 = kc * 32;
        {
            const uint4* s = reinterpret_cast<const uint4*>(
                g_axh_h + (size_t)(m0 + crow) * 256 + k0 + chal);
            *reinterpret_cast<uint4*>(&Ah[crow][chal])     = __ldg(s);
            *reinterpret_cast<uint4*>(&Ah[crow][chal + 8]) = __ldg(s + 1);
            s = reinterpret_cast<const uint4*>(
                g_axh_l + (size_t)(m0 + crow) * 256 + k0 + chal);
            *reinterpret_cast<uint4*>(&Al[crow][chal])     = __ldg(s);
            *reinterpret_cast<uint4*>(&Al[crow][chal + 8]) = __ldg(s + 1);
            s = reinterpret_cast<const uint4*>(WAh + (size_t)crow * 256 + k0 + chal);
            *reinterpret_cast<uint4*>(&Bh[crow][chal])     = __ldg(s);
            *reinterpret_cast<uint4*>(&Bh[crow][chal + 8]) = __ldg(s + 1);
            s = reinterpret_cast<const uint4*>(WAl + (size_t)crow * 256 + k0 + chal);
            *reinterpret_cast<uint4*>(&Bl[crow][chal])     = __ldg(s);
            *reinterpret_cast<uint4*>(&Bl[crow][chal + 8]) = __ldg(s + 1);
        }
        __syncthreads();
#pragma unroll
        for (int s = 0; s < 2; ++s) {             // 2 ksteps of 16
            const int kb = s * 16 + tig * 2;
            uint32_t fah[4][4], fal[4][4], fbh[4][2], fbl[4][2];
#pragma unroll
            for (int fm = 0; fm < 4; ++fm) {
                int r = wm * 64 + fm * 16 + gid;
                fah[fm][0] = *reinterpret_cast<const uint32_t*>(&Ah[r][kb]);
                fah[fm][1] = *reinterpret_cast<const uint32_t*>(&Ah[r + 8][kb]);
                fah[fm][2] = *reinterpret_cast<const uint32_t*>(&Ah[r][kb + 8]);
                fah[fm][3] = *reinterpret_cast<const uint32_t*>(&Ah[r + 8][kb + 8]);
                fal[fm][0] = *reinterpret_cast<const uint32_t*>(&Al[r][kb]);
                fal[fm][1] = *reinterpret_cast<const uint32_t*>(&Al[r + 8][kb]);
                fal[fm][2] = *reinterpret_cast<const uint32_t*>(&Al[r][kb + 8]);
                fal[fm][3] = *reinterpret_cast<const uint32_t*>(&Al[r + 8][kb + 8]);
            }
#pragma unroll
            for (int fn = 0; fn < 4; ++fn) {
                int n = wn * 32 + fn * 8 + gid;
                fbh[fn][0] = *reinterpret_cast<const uint32_t*>(&Bh[n][kb]);
                fbh[fn][1] = *reinterpret_cast<const uint32_t*>(&Bh[n][kb + 8]);
                fbl[fn][0] = *reinterpret_cast<const uint32_t*>(&Bl[n][kb]);
                fbl[fn][1] = *reinterpret_cast<const uint32_t*>(&Bl[n][kb + 8]);
            }
#pragma unroll
            for (int fm = 0; fm < 4; ++fm)
#pragma unroll
                for (int fn = 0; fn < 4; ++fn) {
                    mma16816(acc[fm][fn], fah[fm], fbh[fn]);
                    mma16816(acc[fm][fn], fah[fm], fbl[fn]);
                    mma16816(acc[fm][fn], fal[fm], fbh[fn]);
                }
        }
        __syncthreads();
    }

    // Epilogue
    const int g0 = 2 * j;
#pragma unroll
    for (int fm = 0; fm < 4; ++fm) {
        int rbase = m0 + wm * 64 + fm * 16 + gid;
#pragma unroll
        for (int half = 0; half < 2; ++half) {
            int m = rbase + half * 8;
            if (m >= Nn) continue;
            size_t rowb = (size_t)m * H;
#pragma unroll
            for (int fn = 0; fn < 4; ++fn) {
                int c = wn * 32 + fn * 8 + tig * 2;
                float bias0 = __ldg(bl + g0 * H + c)     + __ldg(bl + (g0 + 1) * H + c);
                float bias1 = __ldg(bl + g0 * H + c + 1) + __ldg(bl + (g0 + 1) * H + c + 1);
                float v0 = acc[fm][fn][half * 2 + 0] + bias0;
                float v1 = acc[fm][fn][half * 2 + 1] + bias1;
                if (j == 0) {
                    float2 o = make_float2(sigmoidf_(v0), sigmoidf_(v1));
                    *reinterpret_cast<float2*>(g_z + rowb + c) = o;
                } else if (j == 1) {
                    float2 hv = *reinterpret_cast<const float2*>(hl + rowb + c);
                    float2 o = make_float2(sigmoidf_(v0) * hv.x, sigmoidf_(v1) * hv.y);
                    *reinterpret_cast<float2*>(g_rh + rowb + c) = o;
                    // fp16 copy for the neighbor gather
                    __half2 o16 = __floats2half2_rn(o.x, o.y);
                    *reinterpret_cast<__half2*>(g_rh16 + rowb + c) = o16;
                } else {
                    *reinterpret_cast<float2*>(g_hx + rowb + c) = make_float2(v0, v1);
                }
            }
        }
    }
}

// ======================= mma.sync GEMM C ===================================
__global__ __launch_bounds__(256)
void gemmC_mma(const float* __restrict__ hl, int layer,
               float* __restrict__ out, int Nn) {
    __shared__ __nv_bfloat16 Ah[128][SST], Al[128][SST];
    __shared__ __nv_bfloat16 Bh[128][SST], Bl[128][SST];

    const int tid  = threadIdx.x;
    const int wid  = tid >> 5;
    const int lane = tid & 31;
    const int gid  = lane >> 2;
    const int tig  = lane & 3;
    const int wm   = wid & 1;
    const int wn   = wid >> 1;
    const int m0   = blockIdx.x * 128;

    const __nv_bfloat16* WCh = g_WCh + (size_t)layer * 128 * 128;
    const __nv_bfloat16* WCl = g_WCl + (size_t)layer * 128 * 128;

    const int crow = tid >> 1;
    const int chal = (tid & 1) * 16;

    float acc[4][4][4];
#pragma unroll
    for (int a = 0; a < 4; a++)
#pragma unroll
        for (int b = 0; b < 4; b++)
#pragma unroll
            for (int c = 0; c < 4; c++) acc[a][b][c] = 0.f;

    for (int kc = 0; kc < 4; ++kc) {        // K = 128, BK = 32
        const int k0 = kc * 32;
        {
            const uint4* s = reinterpret_cast<const uint4*>(
                g_arh_h + (size_t)(m0 + crow) * 128 + k0 + chal);
            *reinterpret_cast<uint4*>(&Ah[crow][chal])     = __ldg(s);
            *reinterpret_cast<uint4*>(&Ah[crow][chal + 8]) = __ldg(s + 1);
            s = reinterpret_cast<const uint4*>(
                g_arh_l + (size_t)(m0 + crow) * 128 + k0 + chal);
            *reinterpret_cast<uint4*>(&Al[crow][chal])     = __ldg(s);
            *reinterpret_cast<uint4*>(&Al[crow][chal + 8]) = __ldg(s + 1);
            s = reinterpret_cast<const uint4*>(WCh + (size_t)crow * 128 + k0 + chal);
            *reinterpret_cast<uint4*>(&Bh[crow][chal])     = __ldg(s);
            *reinterpret_cast<uint4*>(&Bh[crow][chal + 8]) = __ldg(s + 1);
            s = reinterpret_cast<const uint4*>(WCl + (size_t)crow * 128 + k0 + chal);
            *reinterpret_cast<uint4*>(&Bl[crow][chal])     = __ldg(s);
            *reinterpret_cast<uint4*>(&Bl[crow][chal + 8]) = __ldg(s + 1);
        }
        __syncthreads();
#pragma unroll
        for (int s = 0; s < 2; ++s) {
            const int kb = s * 16 + tig * 2;
            uint32_t fah[4][4], fal[4][4], fbh[4][2], fbl[4][2];
#pragma unroll
            for (int fm = 0; fm < 4; ++fm) {
                int r = wm * 64 + fm * 16 + gid;
                fah[fm][0] = *reinterpret_cast<const uint32_t*>(&Ah[r][kb]);
                fah[fm][1] = *reinterpret_cast<const uint32_t*>(&Ah[r + 8][kb]);
                fah[fm][2] = *reinterpret_cast<const uint32_t*>(&Ah[r][kb + 8]);
                fah[fm][3] = *reinterpret_cast<const uint32_t*>(&Ah[r + 8][kb + 8]);
                fal[fm][0] = *reinterpret_cast<const uint32_t*>(&Al[r][kb]);
                fal[fm][1] = *reinterpret_cast<const uint32_t*>(&Al[r + 8][kb]);
                fal[fm][2] = *reinterpret_cast<const uint32_t*>(&Al[r][kb + 8]);
                fal[fm][3] = *reinterpret_cast<const uint32_t*>(&Al[r + 8][kb + 8]);
            }
#pragma unroll
            for (int fn = 0; fn < 4; ++fn) {
                int n = wn * 32 + fn * 8 + gid;
                fbh[fn][0] = *reinterpret_cast<const uint32_t*>(&Bh[n][kb]);
                fbh[fn][1] = *reinterpret_cast<const uint32_t*>(&Bh[n][kb + 8]);
                fbl[fn][0] = *reinterpret_cast<const uint32_t*>(&Bl[n][kb]);
                fbl[fn][1] = *reinterpret_cast<const uint32_t*>(&Bl[n][kb + 8]);
            }
#pragma unroll
            for (int fm = 0; fm < 4; ++fm)
#pragma unroll
                for (int fn = 0; fn < 4; ++fn) {
                    mma16816(acc[fm][fn], fah[fm], fbh[fn]);
                    mma16816(acc[fm][fn], fah[fm], fbl[fn]);
                    mma16816(acc[fm][fn], fal[fm], fbh[fn]);
                }
        }
        __syncthreads();
    }

    // Epilogue: out = z*h + (1-z)*tanh(v + hx)
#pragma unroll
    for (int fm = 0; fm < 4; ++fm) {
        int rbase = m0 + wm * 64 + fm * 16 + gid;
#pragma unroll
        for (int half = 0; half < 2; ++half) {
            int m = rbase + half * 8;
            if (m >= Nn) continue;
            size_t rowb = (size_t)m * H;
#pragma unroll
            for (int fn = 0; fn < 4; ++fn) {
                int c = wn * 32 + fn * 8 + tig * 2;
                float2 hx = *reinterpret_cast<const float2*>(g_hx + rowb + c);
                float2 zz = *reinterpret_cast<const float2*>(g_z + rowb + c);
                float2 hv = *reinterpret_cast<const float2*>(hl + rowb + c);
                float v0 = acc[fm][fn][half * 2 + 0] + hx.x;
                float v1 = acc[fm][fn][half * 2 + 1] + hx.y;
                float2 o;
                o.x = zz.x * hv.x + (1.f - zz.x) * tanhf(v0);
                o.y = zz.y * hv.y + (1.f - zz.y) * tanhf(v1);
                *reinterpret_cast<float2*>(out + rowb + c) = o;
            }
        }
    }
}

// ======================= launch ============================================
extern "C" void kernel_launch(void* const* d_in, const int* in_sizes, int n_in,
                              void* d_out, int out_size) {
    const float* inp = (const float*)d_in[0];
    const int*   edg = (const int*)  d_in[1];
    const float* h   = (const float*)d_in[2];
    const float* W   = (const float*)d_in[3];
    const float* b   = (const float*)d_in[4];
    float* out = (float*)d_out;

    const int Nn = in_sizes[0] / H;          // 50000
    const int E  = in_sizes[1] / 2;          // 1,600,000
    const int L  = in_sizes[2] / (Nn * H);   // 2

    const int* src = edg;
    const int* dst = edg + E;

    const int eblocks = (E + 255) / 256;
    const int nblocks = (Nn + 255) / 256;    // 196
    const int gblocks = (Nn * 32 + 255) / 256;
    const int mblocks = (Nn + 127) / 128;    // 391
    const int n4      = (Nn * H) / 4;
    const int cblocks = (n4 + 255) / 256;

    // CSR build (g_cnt is zero on entry: module-load init + trailing rezero).
    csr_hist_kernel<<<eblocks, 256>>>(dst, E);
    csr_scan1<<<nblocks, 256>>>(Nn);
    csr_scan2<<<nblocks, 256>>>(Nn, E, nblocks);
    csr_fill_kernel<<<eblocks, 256>>>(src, dst, E);
    const int totW = L * 3 * 128 * 256 + L * 128 * 128;
    prep_w_kernel<<<(totW + 255) / 256, 256>>>(W, L);

    for (int i = 0; i < L; i++) {
        const float* x  = (i == 0) ? inp : out + (size_t)(i - 1) * Nn * H;
        const float* hl = h + (size_t)i * Nn * H;
        const float* bl = b + (size_t)i * 6 * H;
        float* outl = out + (size_t)i * Nn * H;

        cvt_xh_kernel<<<cblocks, 256>>>(x, hl, n4);
        gather_xh_kernel<<<gblocks, 256>>>(x, hl, Nn);
        gemmA_mma<<<dim3(mblocks, 3), 256>>>(hl, bl, i, Nn);
        gather_rh_kernel<<<gblocks, 256>>>(Nn);
        gemmC_mma<<<mblocks, 256>>>(hl, i, outl, Nn);
    }

    // Restore invariant for next call.
    csr_rezero<<<nblocks, 256>>>(Nn);
}

// round 13
// speedup vs baseline: 2.8202x; 1.2841x over previous
#include <cuda_runtime.h>
#include <cuda_bf16.h>
#include <math.h>
#include <stdint.h>

// Problem constants (Graph_GRU_84576495993467): N=50000, H=128, L=2, E=1.6M
constexpr int H = 128;
constexpr int NNMAX = 50048;          // 391 * 128 exactly
constexpr int EMAX  = 1605632;
constexpr int LMAX  = 2;

// Scratch (device globals; allocation-free). Zero-initialized at module load.
__device__ __nv_bfloat16 g_axh_h[NNMAX * 256];  // split [ax | ah], hi
__device__ __nv_bfloat16 g_axh_l[NNMAX * 256];  // split [ax | ah], lo
__device__ __nv_bfloat16 g_arh_h[NNMAX * H];
__device__ __nv_bfloat16 g_arh_l[NNMAX * H];
__device__ float g_z   [NNMAX * H];
__device__ float g_rh  [NNMAX * H];
__device__ float g_hx  [NNMAX * H];
__device__ int   g_cnt   [NNMAX];     // invariant: zero at entry of every call
__device__ int   g_rowptr[NNMAX + 1];
__device__ int   g_cursor[NNMAX];
__device__ int   g_col   [EMAX];
__device__ int   g_bsum  [256];
// Pre-split weights, [N,K] layout for mma B operand (row.col => B col-major)
__device__ __nv_bfloat16 g_WAh[LMAX * 3 * 128 * 256];
__device__ __nv_bfloat16 g_WAl[LMAX * 3 * 128 * 256];
__device__ __nv_bfloat16 g_WCh[LMAX * 128 * 128];
__device__ __nv_bfloat16 g_WCl[LMAX * 128 * 128];

__device__ __forceinline__ float4 f4add(float4 a, float4 b) {
    return make_float4(a.x + b.x, a.y + b.y, a.z + b.z, a.w + b.w);
}
__device__ __forceinline__ float sigmoidf_(float v) {
    return 1.0f / (1.0f + __expf(-v));
}
__device__ __forceinline__ uint32_t pk(__nv_bfloat16 a, __nv_bfloat16 b) {
    __nv_bfloat162 t; t.x = a; t.y = b;
    return *reinterpret_cast<uint32_t*>(&t);
}
// Split float4 into hi/lo bf16 packed pairs.
__device__ __forceinline__ void split4(float4 v, uint2& hi, uint2& lo) {
    __nv_bfloat16 h0 = __float2bfloat16_rn(v.x);
    __nv_bfloat16 h1 = __float2bfloat16_rn(v.y);
    __nv_bfloat16 h2 = __float2bfloat16_rn(v.z);
    __nv_bfloat16 h3 = __float2bfloat16_rn(v.w);
    hi = make_uint2(pk(h0, h1), pk(h2, h3));
    lo = make_uint2(pk(__float2bfloat16_rn(v.x - __bfloat162float(h0)),
                       __float2bfloat16_rn(v.y - __bfloat162float(h1))),
                    pk(__float2bfloat16_rn(v.z - __bfloat162float(h2)),
                       __float2bfloat16_rn(v.w - __bfloat162float(h3))));
}

// mma.sync m16n8k16 bf16 -> f32, D += A*B
__device__ __forceinline__ void mma16816(float* d, const uint32_t* a, const uint32_t* b) {
    asm volatile(
        "mma.sync.aligned.m16n8k16.row.col.f32.bf16.bf16.f32 "
        "{%0,%1,%2,%3}, {%4,%5,%6,%7}, {%8,%9}, {%0,%1,%2,%3};"
        : "+f"(d[0]), "+f"(d[1]), "+f"(d[2]), "+f"(d[3])
        : "r"(a[0]), "r"(a[1]), "r"(a[2]), "r"(a[3]), "r"(b[0]), "r"(b[1]));
}

__device__ __forceinline__ uint32_t smem_u32(const void* p) {
    uint32_t a;
    asm("{ .reg .u64 t; cvta.to.shared.u64 t, %1; cvt.u32.u64 %0, t; }"
        : "=r"(a) : "l"(p));
    return a;
}
__device__ __forceinline__ void cpa16(uint32_t dst, const void* src) {
    asm volatile("cp.async.cg.shared.global [%0], [%1], 16;"
                 :: "r"(dst), "l"(src) : "memory");
}
#define CPA_COMMIT() asm volatile("cp.async.commit_group;" ::: "memory")
#define CPA_WAIT(N)  asm volatile("cp.async.wait_group %0;" :: "n"(N) : "memory")

// ======================= CSR build =========================================
__global__ void csr_hist_kernel(const int* __restrict__ dst, int E) {
    int i = blockIdx.x * blockDim.x + threadIdx.x;
    if (i < E) atomicAdd(&g_cnt[__ldg(dst + i)], 1);
}

__global__ __launch_bounds__(256)
void csr_scan1(int Nn) {
    __shared__ int sc[256];
    const int t = threadIdx.x;
    const int i = blockIdx.x * 256 + t;
    int c = (i < Nn) ? g_cnt[i] : 0;
    sc[t] = c;
    __syncthreads();
#pragma unroll
    for (int d = 1; d < 256; d <<= 1) {
        int v = sc[t];
        int vd = (t >= d) ? sc[t - d] : 0;
        __syncthreads();
        sc[t] = v + vd;
        __syncthreads();
    }
    if (i < Nn) g_rowptr[i] = sc[t] - c;   // exclusive within block
    if (t == 255) g_bsum[blockIdx.x] = sc[255];
}

__global__ __launch_bounds__(256)
void csr_scan2(int Nn, int E, int nb) {
    __shared__ int sb[256];
    const int t = threadIdx.x;
    sb[t] = (t < nb) ? g_bsum[t] : 0;
    __syncthreads();
#pragma unroll
    for (int d = 1; d < 256; d <<= 1) {
        int v = sb[t];
        int vd = (t >= d) ? sb[t - d] : 0;
        __syncthreads();
        sb[t] = v + vd;
        __syncthreads();
    }
    const int off = (blockIdx.x > 0) ? sb[blockIdx.x - 1] : 0;
    const int i = blockIdx.x * 256 + t;
    if (i < Nn) {
        int r = g_rowptr[i] + off;
        g_rowptr[i] = r;
        g_cursor[i] = r;
    }
    if (i == 0) g_rowptr[Nn] = E;
}

__global__ void csr_fill_kernel(const int* __restrict__ src,
                                const int* __restrict__ dst, int E) {
    int i = blockIdx.x * blockDim.x + threadIdx.x;
    if (i < E) {
        int d = __ldg(dst + i);
        int pos = atomicAdd(&g_cursor[d], 1);
        g_col[pos] = __ldg(src + i);
    }
}

__global__ void csr_rezero(int Nn) {
    int i = blockIdx.x * blockDim.x + threadIdx.x;
    if (i < Nn) g_cnt[i] = 0;
}

// ======================= Weight pre-split ==================================
__global__ void prep_w_kernel(const float* __restrict__ W, int L) {
    int i = blockIdx.x * blockDim.x + threadIdx.x;
    const int totA = L * 3 * 128 * 256;
    const int totC = L * 128 * 128;
    if (i < totA) {
        int k = i & 255;
        int t = i >> 8;
        int n = t & 127;
        t >>= 7;
        int j = t % 3;
        int l = t / 3;
        int gsel = (k < 128) ? 2 * j : 2 * j + 1;
        int kk = k & 127;
        float v = __ldg(W + (((size_t)l * 6 + gsel) * 128 + kk) * 128 + n);
        __nv_bfloat16 hv = __float2bfloat16_rn(v);
        g_WAh[i] = hv;
        g_WAl[i] = __float2bfloat16_rn(v - __bfloat162float(hv));
    } else if (i < totA + totC) {
        int q = i - totA;
        int k = q & 127;
        int t = q >> 7;
        int n = t & 127;
        int l = t >> 7;
        float v = __ldg(W + (((size_t)l * 6 + 5) * 128 + k) * 128 + n);
        __nv_bfloat16 hv = __float2bfloat16_rn(v);
        g_WCh[q] = hv;
        g_WCl[q] = __float2bfloat16_rn(v - __bfloat162float(hv));
    }
}

// ======================= Gather kernels (fp32, emit split bf16) ============
__global__ __launch_bounds__(256)
void gather_xh_kernel(const float* __restrict__ x,
                      const float* __restrict__ hl, int Nn) {
    int w = (blockIdx.x * blockDim.x + threadIdx.x) >> 5;
    if (w >= Nn) return;
    const int lane = threadIdx.x & 31;
    const int off = lane << 2;
    const int start = __ldg(g_rowptr + w);
    const int end   = __ldg(g_rowptr + w + 1);

    float4 ax = __ldg(reinterpret_cast<const float4*>(x  + (size_t)w * H + off));
    float4 ah = __ldg(reinterpret_cast<const float4*>(hl + (size_t)w * H + off));

    for (int j = start; j < end; j += 32) {
        int rem = end - j;
        int idx = (lane < rem) ? __ldg(g_col + j + lane) : 0;
        int m = min(rem, 32);
#pragma unroll 4
        for (int k = 0; k < m; ++k) {
            int s = __shfl_sync(0xffffffffu, idx, k);
            ax = f4add(ax, __ldg(reinterpret_cast<const float4*>(x  + (size_t)s * H + off)));
            ah = f4add(ah, __ldg(reinterpret_cast<const float4*>(hl + (size_t)s * H + off)));
        }
    }
    uint2 hi, lo;
    split4(ax, hi, lo);
    *reinterpret_cast<uint2*>(g_axh_h + (size_t)w * 256 + off) = hi;
    *reinterpret_cast<uint2*>(g_axh_l + (size_t)w * 256 + off) = lo;
    split4(ah, hi, lo);
    *reinterpret_cast<uint2*>(g_axh_h + (size_t)w * 256 + 128 + off) = hi;
    *reinterpret_cast<uint2*>(g_axh_l + (size_t)w * 256 + 128 + off) = lo;
}

__global__ __launch_bounds__(256)
void gather_rh_kernel(int Nn) {
    int w = (blockIdx.x * blockDim.x + threadIdx.x) >> 5;
    if (w >= Nn) return;
    const int lane = threadIdx.x & 31;
    const int off = lane << 2;
    const int start = __ldg(g_rowptr + w);
    const int end   = __ldg(g_rowptr + w + 1);

    float4 a = *reinterpret_cast<const float4*>(g_rh + (size_t)w * H + off);

    for (int j = start; j < end; j += 32) {
        int rem = end - j;
        int idx = (lane < rem) ? __ldg(g_col + j + lane) : 0;
        int m = min(rem, 32);
#pragma unroll 4
        for (int k = 0; k < m; ++k) {
            int s = __shfl_sync(0xffffffffu, idx, k);
            a = f4add(a, *reinterpret_cast<const float4*>(g_rh + (size_t)s * H + off));
        }
    }
    uint2 hi, lo;
    split4(a, hi, lo);
    *reinterpret_cast<uint2*>(g_arh_h + (size_t)w * H + off) = hi;
    *reinterpret_cast<uint2*>(g_arh_l + (size_t)w * H + off) = lo;
}

// ======================= Pipelined mma.sync GEMMs ==========================
// Two-stage cp.async double buffering. SMEM: 2 stages x 4 tiles (Ah,Al,Bh,Bl)
// of 128 x SST bf16. Split-bf16: D = Ah*Bh + Ah*Bl + Al*Bh (fp32 accumulate).
constexpr int SST = 40;
constexpr int TSE = 128 * SST;                 // elements per tile
constexpr int DSMEM_BYTES = 2 * 4 * TSE * 2;   // 81920 B

// Issue the 8 cp.async (4 tiles x 32B) for one K-chunk into stage st.
// Sources: A arrays with row stride 'astr', B arrays with row stride 'bstr'.
__device__ __forceinline__ void issue_chunk(
    uint32_t smem_base, int st, int crow, int chal, int k0,
    const __nv_bfloat16* Asrc_h, const __nv_bfloat16* Asrc_l, int astr, int arow,
    const __nv_bfloat16* Bsrc_h, const __nv_bfloat16* Bsrc_l, int bstr) {
    const uint32_t rowoff = (uint32_t)(crow * SST + chal) * 2;
    const uint32_t d0 = smem_base + (uint32_t)(st * 4) * (TSE * 2) + rowoff;
    const __nv_bfloat16* a_h = Asrc_h + (size_t)arow * astr + k0 + chal;
    const __nv_bfloat16* a_l = Asrc_l + (size_t)arow * astr + k0 + chal;
    const __nv_bfloat16* b_h = Bsrc_h + (size_t)crow * bstr + k0 + chal;
    const __nv_bfloat16* b_l = Bsrc_l + (size_t)crow * bstr + k0 + chal;
    cpa16(d0,                    a_h);
    cpa16(d0 + 16,               a_h + 8);
    cpa16(d0 + TSE * 2,          a_l);
    cpa16(d0 + TSE * 2 + 16,     a_l + 8);
    cpa16(d0 + 2 * TSE * 2,      b_h);
    cpa16(d0 + 2 * TSE * 2 + 16, b_h + 8);
    cpa16(d0 + 3 * TSE * 2,      b_l);
    cpa16(d0 + 3 * TSE * 2 + 16, b_l + 8);
}

// Compute one K-chunk (2 ksteps of 16) from stage st into acc.
__device__ __forceinline__ void compute_chunk(
    const __nv_bfloat16* dsm, int st, int wm, int wn, int gid, int tig,
    float acc[4][4][4]) {
    const __nv_bfloat16* Ahp = dsm + (st * 4 + 0) * TSE;
    const __nv_bfloat16* Alp = dsm + (st * 4 + 1) * TSE;
    const __nv_bfloat16* Bhp = dsm + (st * 4 + 2) * TSE;
    const __nv_bfloat16* Blp = dsm + (st * 4 + 3) * TSE;
#pragma unroll
    for (int s = 0; s < 2; ++s) {
        const int kb = s * 16 + tig * 2;
        uint32_t fah[4][4], fal[4][4], fbh[4][2], fbl[4][2];
#pragma unroll
        for (int fm = 0; fm < 4; ++fm) {
            int r = wm * 64 + fm * 16 + gid;
            fah[fm][0] = *reinterpret_cast<const uint32_t*>(&Ahp[r * SST + kb]);
            fah[fm][1] = *reinterpret_cast<const uint32_t*>(&Ahp[(r + 8) * SST + kb]);
            fah[fm][2] = *reinterpret_cast<const uint32_t*>(&Ahp[r * SST + kb + 8]);
            fah[fm][3] = *reinterpret_cast<const uint32_t*>(&Ahp[(r + 8) * SST + kb + 8]);
            fal[fm][0] = *reinterpret_cast<const uint32_t*>(&Alp[r * SST + kb]);
            fal[fm][1] = *reinterpret_cast<const uint32_t*>(&Alp[(r + 8) * SST + kb]);
            fal[fm][2] = *reinterpret_cast<const uint32_t*>(&Alp[r * SST + kb + 8]);
            fal[fm][3] = *reinterpret_cast<const uint32_t*>(&Alp[(r + 8) * SST + kb + 8]);
        }
#pragma unroll
        for (int fn = 0; fn < 4; ++fn) {
            int n = wn * 32 + fn * 8 + gid;
            fbh[fn][0] = *reinterpret_cast<const uint32_t*>(&Bhp[n * SST + kb]);
            fbh[fn][1] = *reinterpret_cast<const uint32_t*>(&Bhp[n * SST + kb + 8]);
            fbl[fn][0] = *reinterpret_cast<const uint32_t*>(&Blp[n * SST + kb]);
            fbl[fn][1] = *reinterpret_cast<const uint32_t*>(&Blp[n * SST + kb + 8]);
        }
#pragma unroll
        for (int fm = 0; fm < 4; ++fm)
#pragma unroll
            for (int fn = 0; fn < 4; ++fn) {
                mma16816(acc[fm][fn], fah[fm], fbh[fn]);
                mma16816(acc[fm][fn], fah[fm], fbl[fn]);
                mma16816(acc[fm][fn], fal[fm], fbh[fn]);
            }
    }
}

__global__ __launch_bounds__(256)
void gemmA_mma(const float* __restrict__ hl, const float* __restrict__ bl,
               int layer, int Nn) {
    extern __shared__ __nv_bfloat16 dsm[];
    const uint32_t smem_base = smem_u32(dsm);

    const int tid  = threadIdx.x;
    const int wid  = tid >> 5;
    const int lane = tid & 31;
    const int gid  = lane >> 2;
    const int tig  = lane & 3;
    const int wm   = wid & 1;          // 2 M-warps (64 rows each)
    const int wn   = wid >> 1;         // 4 N-warps (32 cols each)
    const int j    = blockIdx.y;
    const int m0   = blockIdx.x * 128;
    const int nchunks = (j == 2) ? 4 : 8;   // K = 128 or 256, BK = 32

    const __nv_bfloat16* WAh = g_WAh + ((size_t)layer * 3 + j) * 128 * 256;
    const __nv_bfloat16* WAl = g_WAl + ((size_t)layer * 3 + j) * 128 * 256;

    const int crow = tid >> 1;          // copy: row 0..127
    const int chal = (tid & 1) * 16;    // copy: 16-col half
    const int arow = m0 + crow;

    float acc[4][4][4];
#pragma unroll
    for (int a = 0; a < 4; a++)
#pragma unroll
        for (int b = 0; b < 4; b++)
#pragma unroll
            for (int c = 0; c < 4; c++) acc[a][b][c] = 0.f;

    issue_chunk(smem_base, 0, crow, chal, 0,
                g_axh_h, g_axh_l, 256, arow, WAh, WAl, 256);
    CPA_COMMIT();

    for (int kc = 0; kc < nchunks; ++kc) {
        if (kc + 1 < nchunks) {
            issue_chunk(smem_base, (kc + 1) & 1, crow, chal, (kc + 1) * 32,
                        g_axh_h, g_axh_l, 256, arow, WAh, WAl, 256);
            CPA_COMMIT();
            CPA_WAIT(1);
        } else {
            CPA_WAIT(0);
        }
        __syncthreads();
        compute_chunk(dsm, kc & 1, wm, wn, gid, tig, acc);
        __syncthreads();
    }

    // Epilogue
    const int g0 = 2 * j;
#pragma unroll
    for (int fm = 0; fm < 4; ++fm) {
        int rbase = m0 + wm * 64 + fm * 16 + gid;
#pragma unroll
        for (int half = 0; half < 2; ++half) {
            int m = rbase + half * 8;
            if (m >= Nn) continue;
            size_t rowb = (size_t)m * H;
#pragma unroll
            for (int fn = 0; fn < 4; ++fn) {
                int c = wn * 32 + fn * 8 + tig * 2;
                float bias0 = __ldg(bl + g0 * H + c)     + __ldg(bl + (g0 + 1) * H + c);
                float bias1 = __ldg(bl + g0 * H + c + 1) + __ldg(bl + (g0 + 1) * H + c + 1);
                float v0 = acc[fm][fn][half * 2 + 0] + bias0;
                float v1 = acc[fm][fn][half * 2 + 1] + bias1;
                if (j == 0) {
                    float2 o = make_float2(sigmoidf_(v0), sigmoidf_(v1));
                    *reinterpret_cast<float2*>(g_z + rowb + c) = o;
                } else if (j == 1) {
                    float2 hv = *reinterpret_cast<const float2*>(hl + rowb + c);
                    float2 o = make_float2(sigmoidf_(v0) * hv.x, sigmoidf_(v1) * hv.y);
                    *reinterpret_cast<float2*>(g_rh + rowb + c) = o;
                } else {
                    *reinterpret_cast<float2*>(g_hx + rowb + c) = make_float2(v0, v1);
                }
            }
        }
    }
}

__global__ __launch_bounds__(256)
void gemmC_mma(const float* __restrict__ hl, int layer,
               float* __restrict__ out, int Nn) {
    extern __shared__ __nv_bfloat16 dsm[];
    const uint32_t smem_base = smem_u32(dsm);

    const int tid  = threadIdx.x;
    const int wid  = tid >> 5;
    const int lane = tid & 31;
    const int gid  = lane >> 2;
    const int tig  = lane & 3;
    const int wm   = wid & 1;
    const int wn   = wid >> 1;
    const int m0   = blockIdx.x * 128;

    const __nv_bfloat16* WCh = g_WCh + (size_t)layer * 128 * 128;
    const __nv_bfloat16* WCl = g_WCl + (size_t)layer * 128 * 128;

    const int crow = tid >> 1;
    const int chal = (tid & 1) * 16;
    const int arow = m0 + crow;

    float acc[4][4][4];
#pragma unroll
    for (int a = 0; a < 4; a++)
#pragma unroll
        for (int b = 0; b < 4; b++)
#pragma unroll
            for (int c = 0; c < 4; c++) acc[a][b][c] = 0.f;

    issue_chunk(smem_base, 0, crow, chal, 0,
                g_arh_h, g_arh_l, 128, arow, WCh, WCl, 128);
    CPA_COMMIT();

    for (int kc = 0; kc < 4; ++kc) {        // K = 128, BK = 32
        if (kc + 1 < 4) {
            issue_chunk(smem_base, (kc + 1) & 1, crow, chal, (kc + 1) * 32,
                        g_arh_h, g_arh_l, 128, arow, WCh, WCl, 128);
            CPA_COMMIT();
            CPA_WAIT(1);
        } else {
            CPA_WAIT(0);
        }
        __syncthreads();
        compute_chunk(dsm, kc & 1, wm, wn, gid, tig, acc);
        __syncthreads();
    }

    // Epilogue: out = z*h + (1-z)*tanh(v + hx)
#pragma unroll
    for (int fm = 0; fm < 4; ++fm) {
        int rbase = m0 + wm * 64 + fm * 16 + gid;
#pragma unroll
        for (int half = 0; half < 2; ++half) {
            int m = rbase + half * 8;
            if (m >= Nn) continue;
            size_t rowb = (size_t)m * H;
#pragma unroll
            for (int fn = 0; fn < 4; ++fn) {
                int c = wn * 32 + fn * 8 + tig * 2;
                float2 hx = *reinterpret_cast<const float2*>(g_hx + rowb + c);
                float2 zz = *reinterpret_cast<const float2*>(g_z + rowb + c);
                float2 hv = *reinterpret_cast<const float2*>(hl + rowb + c);
                float v0 = acc[fm][fn][half * 2 + 0] + hx.x;
                float v1 = acc[fm][fn][half * 2 + 1] + hx.y;
                float2 o;
                o.x = zz.x * hv.x + (1.f - zz.x) * tanhf(v0);
                o.y = zz.y * hv.y + (1.f - zz.y) * tanhf(v1);
                *reinterpret_cast<float2*>(out + rowb + c) = o;
            }
        }
    }
}

// ======================= launch ============================================
extern "C" void kernel_launch(void* const* d_in, const int* in_sizes, int n_in,
                              void* d_out, int out_size) {
    const float* inp = (const float*)d_in[0];
    const int*   edg = (const int*)  d_in[1];
    const float* h   = (const float*)d_in[2];
    const float* W   = (const float*)d_in[3];
    const float* b   = (const float*)d_in[4];
    float* out = (float*)d_out;

    const int Nn = in_sizes[0] / H;          // 50000
    const int E  = in_sizes[1] / 2;          // 1,600,000
    const int L  = in_sizes[2] / (Nn * H);   // 2

    const int* src = edg;
    const int* dst = edg + E;

    const int eblocks = (E + 255) / 256;
    const int nblocks = (Nn + 255) / 256;    // 196
    const int gblocks = (Nn * 32 + 255) / 256;
    const int mblocks = (Nn + 127) / 128;    // 391

    cudaFuncSetAttribute(gemmA_mma, cudaFuncAttributeMaxDynamicSharedMemorySize, DSMEM_BYTES);
    cudaFuncSetAttribute(gemmC_mma, cudaFuncAttributeMaxDynamicSharedMemorySize, DSMEM_BYTES);

    // CSR build (g_cnt is zero on entry: module-load init + trailing rezero).
    csr_hist_kernel<<<eblocks, 256>>>(dst, E);
    csr_scan1<<<nblocks, 256>>>(Nn);
    csr_scan2<<<nblocks, 256>>>(Nn, E, nblocks);
    csr_fill_kernel<<<eblocks, 256>>>(src, dst, E);
    const int totW = L * 3 * 128 * 256 + L * 128 * 128;
    prep_w_kernel<<<(totW + 255) / 256, 256>>>(W, L);

    for (int i = 0; i < L; i++) {
        const float* x  = (i == 0) ? inp : out + (size_t)(i - 1) * Nn * H;
        const float* hl = h + (size_t)i * Nn * H;
        const float* bl = b + (size_t)i * 6 * H;
        float* outl = out + (size_t)i * Nn * H;

        gather_xh_kernel<<<gblocks, 256>>>(x, hl, Nn);
        gemmA_mma<<<dim3(mblocks, 3), 256, DSMEM_BYTES>>>(hl, bl, i, Nn);
        gather_rh_kernel<<<gblocks, 256>>>(Nn);
        gemmC_mma<<<mblocks, 256, DSMEM_BYTES>>>(hl, i, outl, Nn);
    }

    // Restore invariant for next call.
    csr_rezero<<<nblocks, 256>>>(Nn);
}